// round 10
// baseline (speedup 1.0000x reference)
#include <cuda_runtime.h>
#include <cuda_bf16.h>
#include <math.h>
#include <stdint.h>

// ---------------------------------------------------------------------------
// GatedDeltaNetVarlen  (total=1536, HIDDEN=1024, HK=8, HV=16, DK=DV=64, KSZ=4)
// R10: resubmit of R9 (split-bf16 m16n8k16 GEMM experiment) after container
// flake. C = Ahi*Bhi + Alo*Bhi + Ahi*Blo, f32 accum, 3-stage cp.async.
// ---------------------------------------------------------------------------

#define TOTAL_MAX 1536
#define HIDDEN 1024
#define HK 8
#define HV 16
#define DK 64
#define DV 64
#define KEY_DIM 512
#define VAL_DIM 1024
#define CONV_DIM 2048

__device__ __align__(16) float g_mixed[TOTAL_MAX * CONV_DIM];
__device__ __align__(16) float g_zbuf [TOTAL_MAX * VAL_DIM];
__device__ __align__(16) float g_bbuf [TOTAL_MAX * HV];
__device__ __align__(16) float g_abuf [TOTAL_MAX * HV];
__device__ __align__(16) float g_qn   [TOTAL_MAX * KEY_DIM];
__device__ __align__(16) float g_kn   [TOTAL_MAX * KEY_DIM];
__device__ __align__(16) float g_vv   [TOTAL_MAX * VAL_DIM];
__device__ __align__(16) float g_beta [TOTAL_MAX * HV];
__device__ __align__(16) float g_gate [TOTAL_MAX * HV];
__device__ __align__(16) float g_obuf [TOTAL_MAX * VAL_DIM];
// split bf16 copies (hi + lo; hi+lo reconstructs ~16 mantissa bits)
__device__ __align__(16) __nv_bfloat16 g_hhi [TOTAL_MAX * HIDDEN];
__device__ __align__(16) __nv_bfloat16 g_hlo [TOTAL_MAX * HIDDEN];
__device__ __align__(16) __nv_bfloat16 g_qkvhi[CONV_DIM * HIDDEN];
__device__ __align__(16) __nv_bfloat16 g_qkvlo[CONV_DIM * HIDDEN];
__device__ __align__(16) __nv_bfloat16 g_wzhi [VAL_DIM * HIDDEN];
__device__ __align__(16) __nv_bfloat16 g_wzlo [VAL_DIM * HIDDEN];
__device__ __align__(16) __nv_bfloat16 g_wohi [HIDDEN * VAL_DIM];
__device__ __align__(16) __nv_bfloat16 g_wolo [HIDDEN * VAL_DIM];
__device__ __align__(16) __nv_bfloat16 g_onhi [TOTAL_MAX * VAL_DIM];
__device__ __align__(16) __nv_bfloat16 g_onlo [TOTAL_MAX * VAL_DIM];

// ------------------------------ helpers ------------------------------------
__device__ __forceinline__ unsigned long long pk2(float a, float b) {
    unsigned long long r;
    asm("mov.b64 %0, {%1,%2};" : "=l"(r) : "f"(a), "f"(b));
    return r;
}
__device__ __forceinline__ void upk2(unsigned long long v, float& a, float& b) {
    asm("mov.b64 {%0,%1}, %2;" : "=f"(a), "=f"(b) : "l"(v));
}
__device__ __forceinline__ unsigned long long fma2(
    unsigned long long a, unsigned long long b, unsigned long long c) {
    unsigned long long d;
    asm("fma.rn.f32x2 %0, %1, %2, %3;" : "=l"(d) : "l"(a), "l"(b), "l"(c));
    return d;
}
__device__ __forceinline__ unsigned long long mul2(
    unsigned long long a, unsigned long long b) {
    unsigned long long d;
    asm("mul.rn.f32x2 %0, %1, %2;" : "=l"(d) : "l"(a), "l"(b));
    return d;
}
__device__ __forceinline__ void cpa16(uint32_t dst, const void* src, bool ok) {
    int sz = ok ? 16 : 0;
    asm volatile("cp.async.cg.shared.global [%0], [%1], 16, %2;"
                 :: "r"(dst), "l"(src), "r"(sz) : "memory");
}
__device__ __forceinline__ void split1(float x, __nv_bfloat16& h, __nv_bfloat16& l) {
    h = __float2bfloat16_rn(x);
    l = __float2bfloat16_rn(x - __bfloat162float(h));
}

// ---------------------------------------------------------------------------
// split pre-pass: f32 -> (hi, lo) bf16
// ---------------------------------------------------------------------------
__global__ __launch_bounds__(256) void split_bf16_kernel(
    const float4* __restrict__ s, __nv_bfloat162* __restrict__ hi,
    __nv_bfloat162* __restrict__ lo, int n4)
{
    int i = blockIdx.x * blockDim.x + threadIdx.x;
    if (i < n4) {
        float4 v = s[i];
        __nv_bfloat16 hx, lx, hy, ly, hz, lz, hw, lw;
        split1(v.x, hx, lx); split1(v.y, hy, ly);
        split1(v.z, hz, lz); split1(v.w, hw, lw);
        hi[2 * i]     = __nv_bfloat162(hx, hy);
        hi[2 * i + 1] = __nv_bfloat162(hz, hw);
        lo[2 * i]     = __nv_bfloat162(lx, ly);
        lo[2 * i + 1] = __nv_bfloat162(lz, lw);
    }
}

// ---------------------------------------------------------------------------
// split-bf16 GEMM:  C[M,N] = A[M,K] * B[N,K]^T
// A,B given as hi/lo bf16 pairs. C = Ahi*Bhi + Alo*Bhi + Ahi*Blo (f32 acc).
// 256 threads (8 warps 4m x 2n), BM=128, BN=64, BK=32, warp tile 32x32.
// cp.async 3-stage pipeline. Smem word = bf16x2 pair, pitch 20 words
// (fragment read banks: gid*20+tig mod 32 -> all 32 distinct, conflict-free).
// ---------------------------------------------------------------------------
#define PAD_W 20
#define AH_W (128 * PAD_W)          // words per A half-tile
#define BH_W (64 * PAD_W)
#define STAGE_W (2 * (AH_W + BH_W)) // Ahi+Alo+Bhi+Blo
#define STG 3
#define SMEM_W (STG * STAGE_W)

__global__ __launch_bounds__(256) void gemm_bf16x2(
    const __nv_bfloat16* __restrict__ Ahi, const __nv_bfloat16* __restrict__ Alo,
    const __nv_bfloat16* __restrict__ Bhi, const __nv_bfloat16* __restrict__ Blo,
    float* __restrict__ C, int M, int N, int K)
{
    extern __shared__ unsigned shm[];
    const uint32_t sbase = (uint32_t)__cvta_generic_to_shared(shm);

    const int tid  = threadIdx.x;
    const int lane = tid & 31;
    const int wid  = tid >> 5;
    const int wm   = wid >> 1;        // 0..3
    const int wn   = wid & 1;         // 0..1
    const int gid  = lane >> 2;       // 0..7
    const int tig  = lane & 3;        // 0..3

    const int m0 = blockIdx.y * 128;
    const int n0 = blockIdx.x * 64;

    const int srow  = tid >> 2;       // 0..63
    const int schk  = tid & 3;        // chunk: 8 bf16 = 16B
    const int iters = K / 32;

    auto stage_in = [&](int it) {
        if (it < iters) {
            const int s  = it % STG;
            const int k0 = it * 32;
            const uint32_t sAhi = sbase + (s * STAGE_W) * 4;
            const uint32_t sAlo = sAhi + AH_W * 4;
            const uint32_t sBhi = sAlo + AH_W * 4;
            const uint32_t sBlo = sBhi + BH_W * 4;
            const int koff = k0 + schk * 8;
            const uint32_t woff = schk * 4;   // 4 words per 16B chunk
#pragma unroll
            for (int p = 0; p < 2; p++) {
                int r = srow + 64 * p;
                bool ok = (m0 + r) < M;
                const size_t go = (size_t)(m0 + r) * K + koff;
                cpa16(sAhi + ((r * PAD_W + woff) << 2), Ahi + go, ok);
                cpa16(sAlo + ((r * PAD_W + woff) << 2), Alo + go, ok);
            }
            {
                int r = srow;
                bool ok = (n0 + r) < N;
                const size_t go = (size_t)(n0 + r) * K + koff;
                cpa16(sBhi + ((r * PAD_W + woff) << 2), Bhi + go, ok);
                cpa16(sBlo + ((r * PAD_W + woff) << 2), Blo + go, ok);
            }
        }
        asm volatile("cp.async.commit_group;" ::: "memory");
    };

    float acc[2][4][4];
#pragma unroll
    for (int i = 0; i < 2; i++)
#pragma unroll
        for (int j = 0; j < 4; j++)
#pragma unroll
            for (int v = 0; v < 4; v++) acc[i][j][v] = 0.f;

    stage_in(0);
    stage_in(1);

#define MMA_BF16(ai, bi) \
    asm volatile( \
        "mma.sync.aligned.m16n8k16.row.col.f32.bf16.bf16.f32 " \
        "{%0,%1,%2,%3}, {%4,%5,%6,%7}, {%8,%9}, {%0,%1,%2,%3};" \
        : "+f"(acc[mt][nt][0]), "+f"(acc[mt][nt][1]), \
          "+f"(acc[mt][nt][2]), "+f"(acc[mt][nt][3]) \
        : "r"(ai[mt][0]), "r"(ai[mt][1]), "r"(ai[mt][2]), "r"(ai[mt][3]), \
          "r"(bi[nt][0]), "r"(bi[nt][1]))

    for (int it = 0; it < iters; it++) {
        asm volatile("cp.async.wait_group 1;" ::: "memory");
        __syncthreads();
        stage_in(it + 2);

        const int s = it % STG;
        const unsigned* Ah = shm + s * STAGE_W;
        const unsigned* Al = Ah + AH_W;
        const unsigned* Bh = Al + AH_W;
        const unsigned* Bl = Bh + BH_W;

#pragma unroll
        for (int ks = 0; ks < 2; ks++) {       // two k16 steps per BK=32
            const int kb = ks * 8;             // k-pair base
            unsigned ah[2][4], al[2][4], bh[4][2], bl[4][2];
#pragma unroll
            for (int mt = 0; mt < 2; mt++) {
                int mr = wm * 32 + mt * 16 + gid;
                ah[mt][0] = Ah[mr * PAD_W + kb + tig];
                ah[mt][1] = Ah[(mr + 8) * PAD_W + kb + tig];
                ah[mt][2] = Ah[mr * PAD_W + kb + tig + 4];
                ah[mt][3] = Ah[(mr + 8) * PAD_W + kb + tig + 4];
                al[mt][0] = Al[mr * PAD_W + kb + tig];
                al[mt][1] = Al[(mr + 8) * PAD_W + kb + tig];
                al[mt][2] = Al[mr * PAD_W + kb + tig + 4];
                al[mt][3] = Al[(mr + 8) * PAD_W + kb + tig + 4];
            }
#pragma unroll
            for (int nt = 0; nt < 4; nt++) {
                int nr = wn * 32 + nt * 8 + gid;
                bh[nt][0] = Bh[nr * PAD_W + kb + tig];
                bh[nt][1] = Bh[nr * PAD_W + kb + tig + 4];
                bl[nt][0] = Bl[nr * PAD_W + kb + tig];
                bl[nt][1] = Bl[nr * PAD_W + kb + tig + 4];
            }
#pragma unroll
            for (int mt = 0; mt < 2; mt++)
#pragma unroll
                for (int nt = 0; nt < 4; nt++) {
                    MMA_BF16(al, bh);   // low-order terms first
                    MMA_BF16(ah, bl);
                    MMA_BF16(ah, bh);
                }
        }
    }

    // epilogue (c0,c1 -> row gid, cols tig*2..+1; c2,c3 -> row gid+8)
#pragma unroll
    for (int mt = 0; mt < 2; mt++) {
        int row = m0 + wm * 32 + mt * 16 + gid;
#pragma unroll
        for (int nt = 0; nt < 4; nt++) {
            int col = n0 + wn * 32 + nt * 8 + tig * 2;
            if (row < M)
                *(float2*)(C + (size_t)row * N + col) =
                    make_float2(acc[mt][nt][0], acc[mt][nt][1]);
            if (row + 8 < M)
                *(float2*)(C + (size_t)(row + 8) * N + col) =
                    make_float2(acc[mt][nt][2], acc[mt][nt][3]);
        }
    }
}

// ---------------------------------------------------------------------------
// Fused small projections: b = h@W_b^T, a = h@W_a^T  (N=16 each).
// ---------------------------------------------------------------------------
__global__ __launch_bounds__(128) void small_proj_kernel(
    const float* __restrict__ hs,
    const float* __restrict__ W_b, const float* __restrict__ W_a)
{
    const int t = blockIdx.x;
    __shared__ float sh[HIDDEN];
    {
        const float4* hp = (const float4*)(hs + (size_t)t * HIDDEN);
        float4* sp = (float4*)sh;
        sp[threadIdx.x]       = hp[threadIdx.x];
        sp[threadIdx.x + 128] = hp[threadIdx.x + 128];
    }
    __syncthreads();

    const int out  = threadIdx.x >> 2;
    const int part = threadIdx.x & 3;
    const float* W = (out < 16) ? (W_b + (size_t)out * HIDDEN)
                                : (W_a + (size_t)(out - 16) * HIDDEN);
    const float4* W4 = (const float4*)(W + part * 256);
    const float4* S4 = (const float4*)(sh + part * 256);

    float a0 = 0.f, a1 = 0.f;
#pragma unroll 8
    for (int i = 0; i < 64; i += 2) {
        float4 w = W4[i],      s = S4[i];
        float4 w2 = W4[i + 1], s2 = S4[i + 1];
        a0 = fmaf(w.x, s.x, a0);   a0 = fmaf(w.y, s.y, a0);
        a0 = fmaf(w.z, s.z, a0);   a0 = fmaf(w.w, s.w, a0);
        a1 = fmaf(w2.x, s2.x, a1); a1 = fmaf(w2.y, s2.y, a1);
        a1 = fmaf(w2.z, s2.z, a1); a1 = fmaf(w2.w, s2.w, a1);
    }
    float acc = a0 + a1;
    acc += __shfl_xor_sync(0xffffffffu, acc, 1);
    acc += __shfl_xor_sync(0xffffffffu, acc, 2);
    if (part == 0) {
        if (out < 16) g_bbuf[t * HV + out] = acc;
        else          g_abuf[t * HV + (out - 16)] = acc;
    }
}

// ---------------------------------------------------------------------------
// Causal depthwise conv (KSZ=4) + silu + per-head L2 norm + gates.
// ---------------------------------------------------------------------------
__global__ __launch_bounds__(512) void conv_gate_kernel(
    const float* __restrict__ conv_w,
    const float* __restrict__ dt_bias, const float* __restrict__ A_log,
    const int* __restrict__ cu, int nseq)
{
    const int t = blockIdx.x;
    __shared__ float ybuf[CONV_DIM];
    __shared__ float ssq[16];

    int start = 0;
    for (int b = 0; b < nseq; b++) {
        int s = cu[b];
        if (t >= s) start = s;
    }

#pragma unroll
    for (int r = 0; r < 4; r++) {
        int c = threadIdx.x + 512 * r;
        float acc = 0.f;
#pragma unroll
        for (int j = 0; j < 4; j++) {
            int tt = t - 3 + j;
            if (tt >= start)
                acc = fmaf(conv_w[c * 4 + j], g_mixed[(size_t)tt * CONV_DIM + c], acc);
        }
        ybuf[c] = acc / (1.f + expf(-acc));
    }
    __syncthreads();

    {
        int w = threadIdx.x >> 5, lane = threadIdx.x & 31;
        float x0 = ybuf[w * 64 + lane];
        float x1 = ybuf[w * 64 + 32 + lane];
        float s2 = x0 * x0 + x1 * x1;
#pragma unroll
        for (int off = 16; off > 0; off >>= 1)
            s2 += __shfl_xor_sync(0xffffffffu, s2, off);
        if (lane == 0) ssq[w] = s2;
    }
    __syncthreads();

#pragma unroll
    for (int r = 0; r < 4; r++) {
        int c = threadIdx.x + 512 * r;
        float yv = ybuf[c];
        if (c < KEY_DIM) {
            int h = c >> 6;
            g_qn[(size_t)t * KEY_DIM + c] = yv * rsqrtf(ssq[h] + 1e-6f) * 0.125f;
        } else if (c < 2 * KEY_DIM) {
            int cc = c - KEY_DIM;
            int h = cc >> 6;
            g_kn[(size_t)t * KEY_DIM + cc] = yv * rsqrtf(ssq[8 + h] + 1e-6f);
        } else {
            g_vv[(size_t)t * VAL_DIM + (c - 2 * KEY_DIM)] = yv;
        }
    }

    if (threadIdx.x < HV) {
        int h = threadIdx.x;
        float bb = g_bbuf[t * HV + h];
        g_beta[t * HV + h] = 1.f / (1.f + expf(-bb));
        float aa = g_abuf[t * HV + h] + dt_bias[h];
        float sp = (aa > 20.f) ? aa : log1pf(expf(aa));
        g_gate[t * HV + h] = -expf(A_log[h]) * sp;
    }
}

// ---------------------------------------------------------------------------
// Gated delta rule recurrence, f32x2 packed math.
// grid (HV, nseq, 2); 128 threads: column c = tid>>2, row-group r = tid&3.
// ---------------------------------------------------------------------------
__global__ __launch_bounds__(128) void delta_kernel(const int* __restrict__ cu)
{
    const int h  = blockIdx.x;
    const int b  = blockIdx.y;
    const int j  = blockIdx.z * 32 + (threadIdx.x >> 2);
    const int r  = threadIdx.x & 3;
    const int i0 = r * 16;
    const int kh = h >> 1;
    const int start = cu[b], end = cu[b + 1];

    unsigned long long S2[8];
#pragma unroll
    for (int i = 0; i < 8; i++) S2[i] = 0ULL;

    unsigned long long K2[8], Q2[8], Kn[8], Qn[8];
    float vc, gc, bc, vn, gn, bn;

    auto loadT = [&](int t, unsigned long long* kk, unsigned long long* qq,
                     float& v_, float& g_, float& b_) {
        const ulonglong2* kp = (const ulonglong2*)(g_kn + (size_t)t * KEY_DIM + kh * DK + i0);
        const ulonglong2* qp = (const ulonglong2*)(g_qn + (size_t)t * KEY_DIM + kh * DK + i0);
#pragma unroll
        for (int m = 0; m < 4; m++) {
            ulonglong2 ku = kp[m], qu = qp[m];
            kk[2 * m] = ku.x; kk[2 * m + 1] = ku.y;
            qq[2 * m] = qu.x; qq[2 * m + 1] = qu.y;
        }
        v_ = g_vv[(size_t)t * VAL_DIM + h * DV + j];
        g_ = g_gate[t * HV + h];
        b_ = g_beta[t * HV + h];
    };

    if (start < end) loadT(start, K2, Q2, vc, gc, bc);

    for (int t = start; t < end; t++) {
        int tn = (t + 1 < end) ? (t + 1) : t;
        loadT(tn, Kn, Qn, vn, gn, bn);

        const float dec = expf(gc);

        unsigned long long p0 = 0ULL, p1 = 0ULL;
#pragma unroll
        for (int m = 0; m < 8; m += 2) {
            p0 = fma2(K2[m],     S2[m],     p0);
            p1 = fma2(K2[m + 1], S2[m + 1], p1);
        }
        float lo0, hi0, lo1, hi1;
        upk2(p0, lo0, hi0); upk2(p1, lo1, hi1);
        float ks = (lo0 + hi0) + (lo1 + hi1);
        ks += __shfl_xor_sync(0xffffffffu, ks, 1);
        ks += __shfl_xor_sync(0xffffffffu, ks, 2);

        const float delta = bc * (vc - dec * ks);
        const unsigned long long d2 = pk2(delta, delta);
        const unsigned long long dc2 = pk2(dec, dec);

        unsigned long long o0 = 0ULL, o1 = 0ULL;
#pragma unroll
        for (int m = 0; m < 8; m += 2) {
            unsigned long long kd0 = mul2(K2[m], d2);
            unsigned long long kd1 = mul2(K2[m + 1], d2);
            S2[m]     = fma2(dc2, S2[m],     kd0);
            S2[m + 1] = fma2(dc2, S2[m + 1], kd1);
            o0 = fma2(Q2[m],     S2[m],     o0);
            o1 = fma2(Q2[m + 1], S2[m + 1], o1);
        }
        upk2(o0, lo0, hi0); upk2(o1, lo1, hi1);
        float oo = (lo0 + hi0) + (lo1 + hi1);
        oo += __shfl_xor_sync(0xffffffffu, oo, 1);
        oo += __shfl_xor_sync(0xffffffffu, oo, 2);
        if (r == 0) g_obuf[(size_t)t * VAL_DIM + h * DV + j] = oo;

#pragma unroll
        for (int m = 0; m < 8; m++) { K2[m] = Kn[m]; Q2[m] = Qn[m]; }
        vc = vn; gc = gn; bc = bn;
    }
}

// ---------------------------------------------------------------------------
// Gated RMSNorm; output stored as split bf16 (feeds out-projection GEMM).
// ---------------------------------------------------------------------------
__global__ __launch_bounds__(256) void gated_norm_kernel(const float* __restrict__ nw)
{
    const int t = blockIdx.x;
    const int tid = threadIdx.x;
    const int h = tid >> 4;
    const int s = tid & 15;

    const size_t base = ((size_t)t * HV + h) * DV + s * 4;
    float4 o4 = *(const float4*)(g_obuf + base);
    float ss = o4.x * o4.x + o4.y * o4.y + o4.z * o4.z + o4.w * o4.w;
    ss += __shfl_xor_sync(0xffffffffu, ss, 8);
    ss += __shfl_xor_sync(0xffffffffu, ss, 4);
    ss += __shfl_xor_sync(0xffffffffu, ss, 2);
    ss += __shfl_xor_sync(0xffffffffu, ss, 1);
    const float rr = rsqrtf(ss * (1.f / 64.f) + 1e-6f);

    float4 z4 = *(const float4*)(g_zbuf + (size_t)t * VAL_DIM + h * DV + s * 4);
    float4 w4 = *(const float4*)(nw + s * 4);
    float ox = o4.x * rr * w4.x * (z4.x / (1.f + expf(-z4.x)));
    float oy = o4.y * rr * w4.y * (z4.y / (1.f + expf(-z4.y)));
    float oz = o4.z * rr * w4.z * (z4.z / (1.f + expf(-z4.z)));
    float ow = o4.w * rr * w4.w * (z4.w / (1.f + expf(-z4.w)));

    __nv_bfloat16 hx, lx, hy, ly, hz, lz, hw, lw;
    split1(ox, hx, lx); split1(oy, hy, ly);
    split1(oz, hz, lz); split1(ow, hw, lw);
    *(__nv_bfloat162*)(g_onhi + base)     = __nv_bfloat162(hx, hy);
    *(__nv_bfloat162*)(g_onhi + base + 2) = __nv_bfloat162(hz, hw);
    *(__nv_bfloat162*)(g_onlo + base)     = __nv_bfloat162(lx, ly);
    *(__nv_bfloat162*)(g_onlo + base + 2) = __nv_bfloat162(lz, lw);
}

// ---------------------------------------------------------------------------
extern "C" void kernel_launch(void* const* d_in, const int* in_sizes, int n_in,
                              void* d_out, int out_size)
{
    const float* hidden  = (const float*)d_in[0];
    const float* W_qkv   = (const float*)d_in[1];
    const float* W_z     = (const float*)d_in[2];
    const float* W_b     = (const float*)d_in[3];
    const float* W_a     = (const float*)d_in[4];
    const float* conv_w  = (const float*)d_in[5];
    const float* dt_bias = (const float*)d_in[6];
    const float* A_log   = (const float*)d_in[7];
    const float* nw      = (const float*)d_in[8];
    const float* W_out   = (const float*)d_in[9];
    const int*   cu      = (const int*)d_in[10];

    const int total = in_sizes[0] / HIDDEN;
    const int nseq  = in_sizes[10] - 1;

    float *mixed, *zb;
    __nv_bfloat16 *hhi, *hlo, *qkvhi, *qkvlo, *wzhi, *wzlo, *wohi, *wolo, *onhi, *onlo;
    cudaGetSymbolAddress((void**)&mixed, g_mixed);
    cudaGetSymbolAddress((void**)&zb,    g_zbuf);
    cudaGetSymbolAddress((void**)&hhi,   g_hhi);
    cudaGetSymbolAddress((void**)&hlo,   g_hlo);
    cudaGetSymbolAddress((void**)&qkvhi, g_qkvhi);
    cudaGetSymbolAddress((void**)&qkvlo, g_qkvlo);
    cudaGetSymbolAddress((void**)&wzhi,  g_wzhi);
    cudaGetSymbolAddress((void**)&wzlo,  g_wzlo);
    cudaGetSymbolAddress((void**)&wohi,  g_wohi);
    cudaGetSymbolAddress((void**)&wolo,  g_wolo);
    cudaGetSymbolAddress((void**)&onhi,  g_onhi);
    cudaGetSymbolAddress((void**)&onlo,  g_onlo);

    const int smem_bytes = SMEM_W * 4;
    cudaFuncSetAttribute(gemm_bf16x2, cudaFuncAttributeMaxDynamicSharedMemorySize, smem_bytes);

    // 0. split pre-pass
    {
        int n4;
        n4 = total * HIDDEN / 4;
        split_bf16_kernel<<<(n4 + 255) / 256, 256>>>(
            (const float4*)hidden, (__nv_bfloat162*)hhi, (__nv_bfloat162*)hlo, n4);
        n4 = CONV_DIM * HIDDEN / 4;
        split_bf16_kernel<<<(n4 + 255) / 256, 256>>>(
            (const float4*)W_qkv, (__nv_bfloat162*)qkvhi, (__nv_bfloat162*)qkvlo, n4);
        n4 = VAL_DIM * HIDDEN / 4;
        split_bf16_kernel<<<(n4 + 255) / 256, 256>>>(
            (const float4*)W_z, (__nv_bfloat162*)wzhi, (__nv_bfloat162*)wzlo, n4);
        n4 = HIDDEN * VAL_DIM / 4;
        split_bf16_kernel<<<(n4 + 255) / 256, 256>>>(
            (const float4*)W_out, (__nv_bfloat162*)wohi, (__nv_bfloat162*)wolo, n4);
    }

    const int mB = (total + 127) / 128;

    // 1. big projections (split-bf16 mma)
    gemm_bf16x2<<<dim3(CONV_DIM / 64, mB), 256, smem_bytes>>>(
        hhi, hlo, qkvhi, qkvlo, mixed, total, CONV_DIM, HIDDEN);
    gemm_bf16x2<<<dim3(VAL_DIM / 64, mB), 256, smem_bytes>>>(
        hhi, hlo, wzhi, wzlo, zb, total, VAL_DIM, HIDDEN);

    // 2. small projections (b, a fused)
    small_proj_kernel<<<total, 128>>>(hidden, W_b, W_a);

    // 3. conv + silu + norms + gates
    conv_gate_kernel<<<total, 512>>>(conv_w, dt_bias, A_log, cu, nseq);

    // 4. recurrence
    delta_kernel<<<dim3(HV, nseq, 2), 128>>>(cu);

    // 5. gated RMSNorm (split output)
    gated_norm_kernel<<<total, 256>>>(nw);

    // 6. output projection
    gemm_bf16x2<<<dim3(VAL_DIM / 64, mB), 256, smem_bytes>>>(
        onhi, onlo, wohi, wolo, (float*)d_out, total, HIDDEN, HIDDEN);
}

// round 11
// speedup vs baseline: 1.1010x; 1.1010x over previous
#include <cuda_runtime.h>
#include <cuda_fp16.h>
#include <cuda_bf16.h>
#include <math.h>
#include <stdint.h>

// ---------------------------------------------------------------------------
// GatedDeltaNetVarlen  (total=1536, HIDDEN=1024, HK=8, HV=16, DK=DV=64, KSZ=4)
// R11: 2-term split-fp16 GEMM (A = hi+lo fp16 near-exact, B = single fp16;
// error ~ tf32/sqrt2) + delta recurrence with single pipelined shfl pass.
// ---------------------------------------------------------------------------

#define TOTAL_MAX 1536
#define HIDDEN 1024
#define HK 8
#define HV 16
#define DK 64
#define DV 64
#define KEY_DIM 512
#define VAL_DIM 1024
#define CONV_DIM 2048

__device__ __align__(16) float g_mixed[TOTAL_MAX * CONV_DIM];
__device__ __align__(16) float g_zbuf [TOTAL_MAX * VAL_DIM];
__device__ __align__(16) float g_bbuf [TOTAL_MAX * HV];
__device__ __align__(16) float g_abuf [TOTAL_MAX * HV];
__device__ __align__(16) float g_qn   [TOTAL_MAX * KEY_DIM];
__device__ __align__(16) float g_kn   [TOTAL_MAX * KEY_DIM];
__device__ __align__(16) float g_vv   [TOTAL_MAX * VAL_DIM];
__device__ __align__(16) float g_beta [TOTAL_MAX * HV];
__device__ __align__(16) float g_gate [TOTAL_MAX * HV];
__device__ __align__(16) float g_obuf [TOTAL_MAX * VAL_DIM];
// fp16 copies: A-side split hi/lo, B-side (weights) single
__device__ __align__(16) __half g_hhi [TOTAL_MAX * HIDDEN];
__device__ __align__(16) __half g_hlo [TOTAL_MAX * HIDDEN];
__device__ __align__(16) __half g_wqkvh[CONV_DIM * HIDDEN];
__device__ __align__(16) __half g_wzh  [VAL_DIM * HIDDEN];
__device__ __align__(16) __half g_woh  [HIDDEN * VAL_DIM];
__device__ __align__(16) __half g_onhi [TOTAL_MAX * VAL_DIM];
__device__ __align__(16) __half g_onlo [TOTAL_MAX * VAL_DIM];

// ------------------------------ helpers ------------------------------------
__device__ __forceinline__ unsigned long long pk2(float a, float b) {
    unsigned long long r;
    asm("mov.b64 %0, {%1,%2};" : "=l"(r) : "f"(a), "f"(b));
    return r;
}
__device__ __forceinline__ void upk2(unsigned long long v, float& a, float& b) {
    asm("mov.b64 {%0,%1}, %2;" : "=f"(a), "=f"(b) : "l"(v));
}
__device__ __forceinline__ unsigned long long fma2(
    unsigned long long a, unsigned long long b, unsigned long long c) {
    unsigned long long d;
    asm("fma.rn.f32x2 %0, %1, %2, %3;" : "=l"(d) : "l"(a), "l"(b), "l"(c));
    return d;
}
__device__ __forceinline__ unsigned long long mul2(
    unsigned long long a, unsigned long long b) {
    unsigned long long d;
    asm("mul.rn.f32x2 %0, %1, %2;" : "=l"(d) : "l"(a), "l"(b));
    return d;
}
__device__ __forceinline__ void cpa16(uint32_t dst, const void* src, bool ok) {
    int sz = ok ? 16 : 0;
    asm volatile("cp.async.cg.shared.global [%0], [%1], 16, %2;"
                 :: "r"(dst), "l"(src), "r"(sz) : "memory");
}
__device__ __forceinline__ void split1h(float x, __half& h, __half& l) {
    h = __float2half_rn(x);
    l = __float2half_rn(x - __half2float(h));
}

// ---------------------------------------------------------------------------
// pre-pass kernels: split f32 -> fp16 hi/lo ; convert f32 -> fp16
// ---------------------------------------------------------------------------
__global__ __launch_bounds__(256) void split_h_kernel(
    const float4* __restrict__ s, __half2* __restrict__ hi,
    __half2* __restrict__ lo, int n4)
{
    int i = blockIdx.x * blockDim.x + threadIdx.x;
    if (i < n4) {
        float4 v = s[i];
        __half hx, lx, hy, ly, hz, lz, hw, lw;
        split1h(v.x, hx, lx); split1h(v.y, hy, ly);
        split1h(v.z, hz, lz); split1h(v.w, hw, lw);
        hi[2 * i]     = __half2(hx, hy);
        hi[2 * i + 1] = __half2(hz, hw);
        lo[2 * i]     = __half2(lx, ly);
        lo[2 * i + 1] = __half2(lz, lw);
    }
}

__global__ __launch_bounds__(256) void cvt_h_kernel(
    const float4* __restrict__ s, __half2* __restrict__ d, int n4)
{
    int i = blockIdx.x * blockDim.x + threadIdx.x;
    if (i < n4) {
        float4 v = s[i];
        d[2 * i]     = __half2(__float2half_rn(v.x), __float2half_rn(v.y));
        d[2 * i + 1] = __half2(__float2half_rn(v.z), __float2half_rn(v.w));
    }
}

// ---------------------------------------------------------------------------
// 2-term split-fp16 GEMM:  C[M,N] = (Ahi+Alo)[M,K] * B[N,K]^T  (f32 accum)
// 256 threads (8 warps 4m x 2n), BM=128, BN=64, BK=32, warp tile 32x32.
// cp.async 3-stage pipeline. Smem word = half2 kpair, pitch 20 words
// (fragment banks 20*gid+tig mod 32 all distinct -> conflict-free).
// ---------------------------------------------------------------------------
#define PAD_W 20
#define AH_W (128 * PAD_W)
#define BH_W (64 * PAD_W)
#define STAGE_W (2 * AH_W + BH_W)   // Ahi + Alo + B
#define STG 3
#define SMEM_W (STG * STAGE_W)

__global__ __launch_bounds__(256) void gemm_fp16_2t(
    const __half* __restrict__ Ahi, const __half* __restrict__ Alo,
    const __half* __restrict__ B, float* __restrict__ C, int M, int N, int K)
{
    extern __shared__ unsigned shm[];
    const uint32_t sbase = (uint32_t)__cvta_generic_to_shared(shm);

    const int tid  = threadIdx.x;
    const int lane = tid & 31;
    const int wid  = tid >> 5;
    const int wm   = wid >> 1;        // 0..3
    const int wn   = wid & 1;         // 0..1
    const int gid  = lane >> 2;       // 0..7
    const int tig  = lane & 3;        // 0..3

    const int m0 = blockIdx.y * 128;
    const int n0 = blockIdx.x * 64;

    const int arow = tid >> 1;        // 0..127
    const int ahalf = tid & 1;        // 0,1 (two 16B chunks each)
    const int brow = tid >> 2;        // 0..63
    const int bchk = tid & 3;         // 0..3
    const int iters = K / 32;

    auto stage_in = [&](int it) {
        if (it < iters) {
            const int s  = it % STG;
            const int k0 = it * 32;
            const uint32_t sAh = sbase + (s * STAGE_W) * 4;
            const uint32_t sAl = sAh + AH_W * 4;
            const uint32_t sB  = sAl + AH_W * 4;
            // A: row arow, halves k0 + ahalf*16 + {0..7, 8..15}
            {
                bool ok = (m0 + arow) < M;
                const size_t go = (size_t)(m0 + arow) * K + k0 + ahalf * 16;
                const uint32_t wo = (arow * PAD_W + ahalf * 8) << 2;
                cpa16(sAh + wo,      Ahi + go,     ok);
                cpa16(sAh + wo + 16, Ahi + go + 8, ok);
                cpa16(sAl + wo,      Alo + go,     ok);
                cpa16(sAl + wo + 16, Alo + go + 8, ok);
            }
            // B: row brow, chunk bchk (8 halves)
            {
                bool ok = (n0 + brow) < N;
                const size_t go = (size_t)(n0 + brow) * K + k0 + bchk * 8;
                cpa16(sB + ((brow * PAD_W + bchk * 4) << 2), B + go, ok);
            }
        }
        asm volatile("cp.async.commit_group;" ::: "memory");
    };

    float acc[2][4][4];
#pragma unroll
    for (int i = 0; i < 2; i++)
#pragma unroll
        for (int j = 0; j < 4; j++)
#pragma unroll
            for (int v = 0; v < 4; v++) acc[i][j][v] = 0.f;

    stage_in(0);
    stage_in(1);

#define MMA_F16(ai, bi) \
    asm volatile( \
        "mma.sync.aligned.m16n8k16.row.col.f32.f16.f16.f32 " \
        "{%0,%1,%2,%3}, {%4,%5,%6,%7}, {%8,%9}, {%0,%1,%2,%3};" \
        : "+f"(acc[mt][nt][0]), "+f"(acc[mt][nt][1]), \
          "+f"(acc[mt][nt][2]), "+f"(acc[mt][nt][3]) \
        : "r"(ai[mt][0]), "r"(ai[mt][1]), "r"(ai[mt][2]), "r"(ai[mt][3]), \
          "r"(bi[nt][0]), "r"(bi[nt][1]))

    for (int it = 0; it < iters; it++) {
        asm volatile("cp.async.wait_group 1;" ::: "memory");
        __syncthreads();
        stage_in(it + 2);

        const int s = it % STG;
        const unsigned* Ah = shm + s * STAGE_W;
        const unsigned* Al = Ah + AH_W;
        const unsigned* Bs = Al + AH_W;

#pragma unroll
        for (int ks = 0; ks < 2; ks++) {
            const int kb = ks * 8;
            unsigned ah[2][4], al[2][4], bf[4][2];
#pragma unroll
            for (int mt = 0; mt < 2; mt++) {
                int mr = wm * 32 + mt * 16 + gid;
                ah[mt][0] = Ah[mr * PAD_W + kb + tig];
                ah[mt][1] = Ah[(mr + 8) * PAD_W + kb + tig];
                ah[mt][2] = Ah[mr * PAD_W + kb + tig + 4];
                ah[mt][3] = Ah[(mr + 8) * PAD_W + kb + tig + 4];
                al[mt][0] = Al[mr * PAD_W + kb + tig];
                al[mt][1] = Al[(mr + 8) * PAD_W + kb + tig];
                al[mt][2] = Al[mr * PAD_W + kb + tig + 4];
                al[mt][3] = Al[(mr + 8) * PAD_W + kb + tig + 4];
            }
#pragma unroll
            for (int nt = 0; nt < 4; nt++) {
                int nr = wn * 32 + nt * 8 + gid;
                bf[nt][0] = Bs[nr * PAD_W + kb + tig];
                bf[nt][1] = Bs[nr * PAD_W + kb + tig + 4];
            }
#pragma unroll
            for (int mt = 0; mt < 2; mt++)
#pragma unroll
                for (int nt = 0; nt < 4; nt++) {
                    MMA_F16(al, bf);    // low-order term first
                    MMA_F16(ah, bf);
                }
        }
    }

    // epilogue
#pragma unroll
    for (int mt = 0; mt < 2; mt++) {
        int row = m0 + wm * 32 + mt * 16 + gid;
#pragma unroll
        for (int nt = 0; nt < 4; nt++) {
            int col = n0 + wn * 32 + nt * 8 + tig * 2;
            if (row < M)
                *(float2*)(C + (size_t)row * N + col) =
                    make_float2(acc[mt][nt][0], acc[mt][nt][1]);
            if (row + 8 < M)
                *(float2*)(C + (size_t)(row + 8) * N + col) =
                    make_float2(acc[mt][nt][2], acc[mt][nt][3]);
        }
    }
}

// ---------------------------------------------------------------------------
// Fused small projections: b = h@W_b^T, a = h@W_a^T  (N=16 each).
// ---------------------------------------------------------------------------
__global__ __launch_bounds__(128) void small_proj_kernel(
    const float* __restrict__ hs,
    const float* __restrict__ W_b, const float* __restrict__ W_a)
{
    const int t = blockIdx.x;
    __shared__ float sh[HIDDEN];
    {
        const float4* hp = (const float4*)(hs + (size_t)t * HIDDEN);
        float4* sp = (float4*)sh;
        sp[threadIdx.x]       = hp[threadIdx.x];
        sp[threadIdx.x + 128] = hp[threadIdx.x + 128];
    }
    __syncthreads();

    const int out  = threadIdx.x >> 2;
    const int part = threadIdx.x & 3;
    const float* W = (out < 16) ? (W_b + (size_t)out * HIDDEN)
                                : (W_a + (size_t)(out - 16) * HIDDEN);
    const float4* W4 = (const float4*)(W + part * 256);
    const float4* S4 = (const float4*)(sh + part * 256);

    float a0 = 0.f, a1 = 0.f;
#pragma unroll 8
    for (int i = 0; i < 64; i += 2) {
        float4 w = W4[i],      s = S4[i];
        float4 w2 = W4[i + 1], s2 = S4[i + 1];
        a0 = fmaf(w.x, s.x, a0);   a0 = fmaf(w.y, s.y, a0);
        a0 = fmaf(w.z, s.z, a0);   a0 = fmaf(w.w, s.w, a0);
        a1 = fmaf(w2.x, s2.x, a1); a1 = fmaf(w2.y, s2.y, a1);
        a1 = fmaf(w2.z, s2.z, a1); a1 = fmaf(w2.w, s2.w, a1);
    }
    float acc = a0 + a1;
    acc += __shfl_xor_sync(0xffffffffu, acc, 1);
    acc += __shfl_xor_sync(0xffffffffu, acc, 2);
    if (part == 0) {
        if (out < 16) g_bbuf[t * HV + out] = acc;
        else          g_abuf[t * HV + (out - 16)] = acc;
    }
}

// ---------------------------------------------------------------------------
// Causal depthwise conv (KSZ=4) + silu + per-head L2 norm + gates.
// ---------------------------------------------------------------------------
__global__ __launch_bounds__(512) void conv_gate_kernel(
    const float* __restrict__ conv_w,
    const float* __restrict__ dt_bias, const float* __restrict__ A_log,
    const int* __restrict__ cu, int nseq)
{
    const int t = blockIdx.x;
    __shared__ float ybuf[CONV_DIM];
    __shared__ float ssq[16];

    int start = 0;
    for (int b = 0; b < nseq; b++) {
        int s = cu[b];
        if (t >= s) start = s;
    }

#pragma unroll
    for (int r = 0; r < 4; r++) {
        int c = threadIdx.x + 512 * r;
        float acc = 0.f;
#pragma unroll
        for (int j = 0; j < 4; j++) {
            int tt = t - 3 + j;
            if (tt >= start)
                acc = fmaf(conv_w[c * 4 + j], g_mixed[(size_t)tt * CONV_DIM + c], acc);
        }
        ybuf[c] = acc / (1.f + expf(-acc));
    }
    __syncthreads();

    {
        int w = threadIdx.x >> 5, lane = threadIdx.x & 31;
        float x0 = ybuf[w * 64 + lane];
        float x1 = ybuf[w * 64 + 32 + lane];
        float s2 = x0 * x0 + x1 * x1;
#pragma unroll
        for (int off = 16; off > 0; off >>= 1)
            s2 += __shfl_xor_sync(0xffffffffu, s2, off);
        if (lane == 0) ssq[w] = s2;
    }
    __syncthreads();

#pragma unroll
    for (int r = 0; r < 4; r++) {
        int c = threadIdx.x + 512 * r;
        float yv = ybuf[c];
        if (c < KEY_DIM) {
            int h = c >> 6;
            g_qn[(size_t)t * KEY_DIM + c] = yv * rsqrtf(ssq[h] + 1e-6f) * 0.125f;
        } else if (c < 2 * KEY_DIM) {
            int cc = c - KEY_DIM;
            int h = cc >> 6;
            g_kn[(size_t)t * KEY_DIM + cc] = yv * rsqrtf(ssq[8 + h] + 1e-6f);
        } else {
            g_vv[(size_t)t * VAL_DIM + (c - 2 * KEY_DIM)] = yv;
        }
    }

    if (threadIdx.x < HV) {
        int h = threadIdx.x;
        float bb = g_bbuf[t * HV + h];
        g_beta[t * HV + h] = 1.f / (1.f + expf(-bb));
        float aa = g_abuf[t * HV + h] + dt_bias[h];
        float sp = (aa > 20.f) ? aa : log1pf(expf(aa));
        g_gate[t * HV + h] = -expf(A_log[h]) * sp;
    }
}

// ---------------------------------------------------------------------------
// Gated delta rule recurrence — single pipelined shfl pass per step.
// o_t = dec*(q.S_old) + (q.k)*delta ; delta = b*(v - dec*(k.S_old)) ;
// S_new = dec*S_old + delta*k.
// grid (HV, nseq, 2); 128 threads: column c = tid>>2, row-group r = tid&3.
// ---------------------------------------------------------------------------
__global__ __launch_bounds__(128) void delta_kernel(const int* __restrict__ cu)
{
    const int h  = blockIdx.x;
    const int b  = blockIdx.y;
    const int j  = blockIdx.z * 32 + (threadIdx.x >> 2);
    const int r  = threadIdx.x & 3;
    const int i0 = r * 16;
    const int kh = h >> 1;
    const int start = cu[b], end = cu[b + 1];

    unsigned long long S2[8];
#pragma unroll
    for (int i = 0; i < 8; i++) S2[i] = 0ULL;

    unsigned long long K2[8], Q2[8], Kn[8], Qn[8];
    float vc, gc, bc, vn, gn, bn;

    auto loadT = [&](int t, unsigned long long* kk, unsigned long long* qq,
                     float& v_, float& g_, float& b_) {
        const ulonglong2* kp = (const ulonglong2*)(g_kn + (size_t)t * KEY_DIM + kh * DK + i0);
        const ulonglong2* qp = (const ulonglong2*)(g_qn + (size_t)t * KEY_DIM + kh * DK + i0);
#pragma unroll
        for (int m = 0; m < 4; m++) {
            ulonglong2 ku = kp[m], qu = qp[m];
            kk[2 * m] = ku.x; kk[2 * m + 1] = ku.y;
            qq[2 * m] = qu.x; qq[2 * m + 1] = qu.y;
        }
        v_ = g_vv[(size_t)t * VAL_DIM + h * DV + j];
        g_ = g_gate[t * HV + h];
        b_ = g_beta[t * HV + h];
    };

    if (start < end) loadT(start, K2, Q2, vc, gc, bc);

    for (int t = start; t < end; t++) {
        int tn = (t + 1 < end) ? (t + 1) : t;
        loadT(tn, Kn, Qn, vn, gn, bn);

        const float dec = expf(gc);

        // three dots: pk = k.S, pq = q.S, pz = q.k  (pz has no S dependency)
        unsigned long long pk0 = 0ULL, pk1 = 0ULL;
        unsigned long long pq0 = 0ULL, pq1 = 0ULL;
        unsigned long long pz0 = 0ULL, pz1 = 0ULL;
#pragma unroll
        for (int m = 0; m < 8; m += 2) {
            pk0 = fma2(K2[m],     S2[m],     pk0);
            pk1 = fma2(K2[m + 1], S2[m + 1], pk1);
            pq0 = fma2(Q2[m],     S2[m],     pq0);
            pq1 = fma2(Q2[m + 1], S2[m + 1], pq1);
            pz0 = fma2(Q2[m],     K2[m],     pz0);
            pz1 = fma2(Q2[m + 1], K2[m + 1], pz1);
        }
        float a0, a1, b0, b1;
        upk2(pk0, a0, a1); upk2(pk1, b0, b1);
        float pk = (a0 + a1) + (b0 + b1);
        upk2(pq0, a0, a1); upk2(pq1, b0, b1);
        float pq = (a0 + a1) + (b0 + b1);
        upk2(pz0, a0, a1); upk2(pz1, b0, b1);
        float pz = (a0 + a1) + (b0 + b1);

        // one pipelined reduction pass (independent shfls dual-issue)
        pk += __shfl_xor_sync(0xffffffffu, pk, 1);
        pq += __shfl_xor_sync(0xffffffffu, pq, 1);
        pz += __shfl_xor_sync(0xffffffffu, pz, 1);
        pk += __shfl_xor_sync(0xffffffffu, pk, 2);
        pq += __shfl_xor_sync(0xffffffffu, pq, 2);
        pz += __shfl_xor_sync(0xffffffffu, pz, 2);

        const float delta = bc * (vc - dec * pk);
        if (r == 0)
            g_obuf[(size_t)t * VAL_DIM + h * DV + j] = dec * pq + delta * pz;

        const unsigned long long d2  = pk2(delta, delta);
        const unsigned long long dc2 = pk2(dec, dec);
#pragma unroll
        for (int m = 0; m < 8; m += 2) {
            S2[m]     = fma2(dc2, S2[m],     mul2(K2[m],     d2));
            S2[m + 1] = fma2(dc2, S2[m + 1], mul2(K2[m + 1], d2));
        }

#pragma unroll
        for (int m = 0; m < 8; m++) { K2[m] = Kn[m]; Q2[m] = Qn[m]; }
        vc = vn; gc = gn; bc = bn;
    }
}

// ---------------------------------------------------------------------------
// Gated RMSNorm; output stored as split fp16 (feeds out-projection GEMM).
// ---------------------------------------------------------------------------
__global__ __launch_bounds__(256) void gated_norm_kernel(const float* __restrict__ nw)
{
    const int t = blockIdx.x;
    const int tid = threadIdx.x;
    const int h = tid >> 4;
    const int s = tid & 15;

    const size_t base = ((size_t)t * HV + h) * DV + s * 4;
    float4 o4 = *(const float4*)(g_obuf + base);
    float ss = o4.x * o4.x + o4.y * o4.y + o4.z * o4.z + o4.w * o4.w;
    ss += __shfl_xor_sync(0xffffffffu, ss, 8);
    ss += __shfl_xor_sync(0xffffffffu, ss, 4);
    ss += __shfl_xor_sync(0xffffffffu, ss, 2);
    ss += __shfl_xor_sync(0xffffffffu, ss, 1);
    const float rr = rsqrtf(ss * (1.f / 64.f) + 1e-6f);

    float4 z4 = *(const float4*)(g_zbuf + (size_t)t * VAL_DIM + h * DV + s * 4);
    float4 w4 = *(const float4*)(nw + s * 4);
    float ox = o4.x * rr * w4.x * (z4.x / (1.f + expf(-z4.x)));
    float oy = o4.y * rr * w4.y * (z4.y / (1.f + expf(-z4.y)));
    float oz = o4.z * rr * w4.z * (z4.z / (1.f + expf(-z4.z)));
    float ow = o4.w * rr * w4.w * (z4.w / (1.f + expf(-z4.w)));

    __half hx, lx, hy, ly, hz, lz, hw, lw;
    split1h(ox, hx, lx); split1h(oy, hy, ly);
    split1h(oz, hz, lz); split1h(ow, hw, lw);
    *(__half2*)(g_onhi + base)     = __half2(hx, hy);
    *(__half2*)(g_onhi + base + 2) = __half2(hz, hw);
    *(__half2*)(g_onlo + base)     = __half2(lx, ly);
    *(__half2*)(g_onlo + base + 2) = __half2(lz, lw);
}

// ---------------------------------------------------------------------------
extern "C" void kernel_launch(void* const* d_in, const int* in_sizes, int n_in,
                              void* d_out, int out_size)
{
    const float* hidden  = (const float*)d_in[0];
    const float* W_qkv   = (const float*)d_in[1];
    const float* W_z     = (const float*)d_in[2];
    const float* W_b     = (const float*)d_in[3];
    const float* W_a     = (const float*)d_in[4];
    const float* conv_w  = (const float*)d_in[5];
    const float* dt_bias = (const float*)d_in[6];
    const float* A_log   = (const float*)d_in[7];
    const float* nw      = (const float*)d_in[8];
    const float* W_out   = (const float*)d_in[9];
    const int*   cu      = (const int*)d_in[10];

    const int total = in_sizes[0] / HIDDEN;
    const int nseq  = in_sizes[10] - 1;

    float *mixed, *zb;
    __half *hhi, *hlo, *wqkvh, *wzh, *woh, *onhi, *onlo;
    cudaGetSymbolAddress((void**)&mixed, g_mixed);
    cudaGetSymbolAddress((void**)&zb,    g_zbuf);
    cudaGetSymbolAddress((void**)&hhi,   g_hhi);
    cudaGetSymbolAddress((void**)&hlo,   g_hlo);
    cudaGetSymbolAddress((void**)&wqkvh, g_wqkvh);
    cudaGetSymbolAddress((void**)&wzh,   g_wzh);
    cudaGetSymbolAddress((void**)&woh,   g_woh);
    cudaGetSymbolAddress((void**)&onhi,  g_onhi);
    cudaGetSymbolAddress((void**)&onlo,  g_onlo);

    const int smem_bytes = SMEM_W * 4;
    cudaFuncSetAttribute(gemm_fp16_2t, cudaFuncAttributeMaxDynamicSharedMemorySize, smem_bytes);

    // 0. fp16 pre-pass: split h; convert weights
    {
        int n4;
        n4 = total * HIDDEN / 4;
        split_h_kernel<<<(n4 + 255) / 256, 256>>>(
            (const float4*)hidden, (__half2*)hhi, (__half2*)hlo, n4);
        n4 = CONV_DIM * HIDDEN / 4;
        cvt_h_kernel<<<(n4 + 255) / 256, 256>>>((const float4*)W_qkv, (__half2*)wqkvh, n4);
        n4 = VAL_DIM * HIDDEN / 4;
        cvt_h_kernel<<<(n4 + 255) / 256, 256>>>((const float4*)W_z, (__half2*)wzh, n4);
        n4 = HIDDEN * VAL_DIM / 4;
        cvt_h_kernel<<<(n4 + 255) / 256, 256>>>((const float4*)W_out, (__half2*)woh, n4);
    }

    const int mB = (total + 127) / 128;

    // 1. big projections (2-term split-fp16 mma)
    gemm_fp16_2t<<<dim3(CONV_DIM / 64, mB), 256, smem_bytes>>>(
        hhi, hlo, wqkvh, mixed, total, CONV_DIM, HIDDEN);
    gemm_fp16_2t<<<dim3(VAL_DIM / 64, mB), 256, smem_bytes>>>(
        hhi, hlo, wzh, zb, total, VAL_DIM, HIDDEN);

    // 2. small projections (b, a fused)
    small_proj_kernel<<<total, 128>>>(hidden, W_b, W_a);

    // 3. conv + silu + norms + gates
    conv_gate_kernel<<<total, 512>>>(conv_w, dt_bias, A_log, cu, nseq);

    // 4. recurrence
    delta_kernel<<<dim3(HV, nseq, 2), 128>>>(cu);

    // 5. gated RMSNorm (split fp16 output)
    gated_norm_kernel<<<total, 256>>>(nw);

    // 6. output projection
    gemm_fp16_2t<<<dim3(VAL_DIM / 64, mB), 256, smem_bytes>>>(
        onhi, onlo, woh, (float*)d_out, total, HIDDEN, HIDDEN);
}

// round 15
// speedup vs baseline: 1.2768x; 1.1597x over previous
#include <cuda_runtime.h>
#include <cuda_fp16.h>
#include <cuda_bf16.h>
#include <math.h>
#include <stdint.h>

// ---------------------------------------------------------------------------
// GatedDeltaNetVarlen  (total=1536, HIDDEN=1024, HK=8, HV=16, DK=DV=64, KSZ=4)
// R12: single-term fp16 mma GEMM (mma.sync costs ~50cyc/instr regardless of
// kind on this build -> minimize instruction count; fp16 == tf32 mantissa).
// ---------------------------------------------------------------------------

#define TOTAL_MAX 1536
#define HIDDEN 1024
#define HK 8
#define HV 16
#define DK 64
#define DV 64
#define KEY_DIM 512
#define VAL_DIM 1024
#define CONV_DIM 2048

__device__ __align__(16) float g_mixed[TOTAL_MAX * CONV_DIM];
__device__ __align__(16) float g_zbuf [TOTAL_MAX * VAL_DIM];
__device__ __align__(16) float g_bbuf [TOTAL_MAX * HV];
__device__ __align__(16) float g_abuf [TOTAL_MAX * HV];
__device__ __align__(16) float g_qn   [TOTAL_MAX * KEY_DIM];
__device__ __align__(16) float g_kn   [TOTAL_MAX * KEY_DIM];
__device__ __align__(16) float g_vv   [TOTAL_MAX * VAL_DIM];
__device__ __align__(16) float g_beta [TOTAL_MAX * HV];
__device__ __align__(16) float g_gate [TOTAL_MAX * HV];
__device__ __align__(16) float g_obuf [TOTAL_MAX * VAL_DIM];
// fp16 copies
__device__ __align__(16) __half g_hh   [TOTAL_MAX * HIDDEN];
__device__ __align__(16) __half g_wqkvh[CONV_DIM * HIDDEN];
__device__ __align__(16) __half g_wzh  [VAL_DIM * HIDDEN];
__device__ __align__(16) __half g_woh  [HIDDEN * VAL_DIM];
__device__ __align__(16) __half g_onh  [TOTAL_MAX * VAL_DIM];

// ------------------------------ helpers ------------------------------------
__device__ __forceinline__ unsigned long long pk2(float a, float b) {
    unsigned long long r;
    asm("mov.b64 %0, {%1,%2};" : "=l"(r) : "f"(a), "f"(b));
    return r;
}
__device__ __forceinline__ void upk2(unsigned long long v, float& a, float& b) {
    asm("mov.b64 {%0,%1}, %2;" : "=f"(a), "=f"(b) : "l"(v));
}
__device__ __forceinline__ unsigned long long fma2(
    unsigned long long a, unsigned long long b, unsigned long long c) {
    unsigned long long d;
    asm("fma.rn.f32x2 %0, %1, %2, %3;" : "=l"(d) : "l"(a), "l"(b), "l"(c));
    return d;
}
__device__ __forceinline__ unsigned long long mul2(
    unsigned long long a, unsigned long long b) {
    unsigned long long d;
    asm("mul.rn.f32x2 %0, %1, %2;" : "=l"(d) : "l"(a), "l"(b));
    return d;
}
__device__ __forceinline__ void cpa16(uint32_t dst, const void* src, bool ok) {
    int sz = ok ? 16 : 0;
    asm volatile("cp.async.cg.shared.global [%0], [%1], 16, %2;"
                 :: "r"(dst), "l"(src), "r"(sz) : "memory");
}

// ---------------------------------------------------------------------------
// pre-pass: convert f32 -> fp16
// ---------------------------------------------------------------------------
__global__ __launch_bounds__(256) void cvt_h_kernel(
    const float4* __restrict__ s, __half2* __restrict__ d, int n4)
{
    int i = blockIdx.x * blockDim.x + threadIdx.x;
    if (i < n4) {
        float4 v = s[i];
        d[2 * i]     = __half2(__float2half_rn(v.x), __float2half_rn(v.y));
        d[2 * i + 1] = __half2(__float2half_rn(v.z), __float2half_rn(v.w));
    }
}

// ---------------------------------------------------------------------------
// single-term fp16 GEMM:  C[M,N] = A[M,K] * B[N,K]^T  (f32 accum)
// 256 threads (8 warps 4m x 2n), BM=128, BN=64, BK=32, warp tile 32x32.
// cp.async 3-stage pipeline. Smem word = half2 kpair, pitch 20 words
// (fragment banks 20*gid+tig mod 32 all distinct -> conflict-free).
// ---------------------------------------------------------------------------
#define PAD_W 20
#define AH_W (128 * PAD_W)
#define BH_W (64 * PAD_W)
#define STAGE_W (AH_W + BH_W)
#define STG 3
#define SMEM_W (STG * STAGE_W)

__global__ __launch_bounds__(256) void gemm_fp16(
    const __half* __restrict__ A, const __half* __restrict__ B,
    float* __restrict__ C, int M, int N, int K)
{
    extern __shared__ unsigned shm[];
    const uint32_t sbase = (uint32_t)__cvta_generic_to_shared(shm);

    const int tid  = threadIdx.x;
    const int lane = tid & 31;
    const int wid  = tid >> 5;
    const int wm   = wid >> 1;        // 0..3
    const int wn   = wid & 1;         // 0..1
    const int gid  = lane >> 2;       // 0..7
    const int tig  = lane & 3;        // 0..3

    const int m0 = blockIdx.y * 128;
    const int n0 = blockIdx.x * 64;

    const int arow = tid >> 1;        // 0..127
    const int ahalf = tid & 1;        // 0,1
    const int brow = tid >> 2;        // 0..63
    const int bchk = tid & 3;         // 0..3
    const int iters = K / 32;

    auto stage_in = [&](int it) {
        if (it < iters) {
            const int s  = it % STG;
            const int k0 = it * 32;
            const uint32_t sA = sbase + (s * STAGE_W) * 4;
            const uint32_t sB = sA + AH_W * 4;
            {
                bool ok = (m0 + arow) < M;
                const size_t go = (size_t)(m0 + arow) * K + k0 + ahalf * 16;
                const uint32_t wo = (arow * PAD_W + ahalf * 8) << 2;
                cpa16(sA + wo,      A + go,     ok);
                cpa16(sA + wo + 16, A + go + 8, ok);
            }
            {
                bool ok = (n0 + brow) < N;
                const size_t go = (size_t)(n0 + brow) * K + k0 + bchk * 8;
                cpa16(sB + ((brow * PAD_W + bchk * 4) << 2), B + go, ok);
            }
        }
        asm volatile("cp.async.commit_group;" ::: "memory");
    };

    float acc[2][4][4];
#pragma unroll
    for (int i = 0; i < 2; i++)
#pragma unroll
        for (int j = 0; j < 4; j++)
#pragma unroll
            for (int v = 0; v < 4; v++) acc[i][j][v] = 0.f;

    stage_in(0);
    stage_in(1);

#define MMA_F16(ai, bi) \
    asm volatile( \
        "mma.sync.aligned.m16n8k16.row.col.f32.f16.f16.f32 " \
        "{%0,%1,%2,%3}, {%4,%5,%6,%7}, {%8,%9}, {%0,%1,%2,%3};" \
        : "+f"(acc[mt][nt][0]), "+f"(acc[mt][nt][1]), \
          "+f"(acc[mt][nt][2]), "+f"(acc[mt][nt][3]) \
        : "r"(ai[mt][0]), "r"(ai[mt][1]), "r"(ai[mt][2]), "r"(ai[mt][3]), \
          "r"(bi[nt][0]), "r"(bi[nt][1]))

    for (int it = 0; it < iters; it++) {
        asm volatile("cp.async.wait_group 1;" ::: "memory");
        __syncthreads();
        stage_in(it + 2);

        const int s = it % STG;
        const unsigned* As = shm + s * STAGE_W;
        const unsigned* Bs = As + AH_W;

#pragma unroll
        for (int ks = 0; ks < 2; ks++) {
            const int kb = ks * 8;
            unsigned af[2][4], bf[4][2];
#pragma unroll
            for (int mt = 0; mt < 2; mt++) {
                int mr = wm * 32 + mt * 16 + gid;
                af[mt][0] = As[mr * PAD_W + kb + tig];
                af[mt][1] = As[(mr + 8) * PAD_W + kb + tig];
                af[mt][2] = As[mr * PAD_W + kb + tig + 4];
                af[mt][3] = As[(mr + 8) * PAD_W + kb + tig + 4];
            }
#pragma unroll
            for (int nt = 0; nt < 4; nt++) {
                int nr = wn * 32 + nt * 8 + gid;
                bf[nt][0] = Bs[nr * PAD_W + kb + tig];
                bf[nt][1] = Bs[nr * PAD_W + kb + tig + 4];
            }
#pragma unroll
            for (int mt = 0; mt < 2; mt++)
#pragma unroll
                for (int nt = 0; nt < 4; nt++) {
                    MMA_F16(af, bf);
                }
        }
    }

    // epilogue
#pragma unroll
    for (int mt = 0; mt < 2; mt++) {
        int row = m0 + wm * 32 + mt * 16 + gid;
#pragma unroll
        for (int nt = 0; nt < 4; nt++) {
            int col = n0 + wn * 32 + nt * 8 + tig * 2;
            if (row < M)
                *(float2*)(C + (size_t)row * N + col) =
                    make_float2(acc[mt][nt][0], acc[mt][nt][1]);
            if (row + 8 < M)
                *(float2*)(C + (size_t)(row + 8) * N + col) =
                    make_float2(acc[mt][nt][2], acc[mt][nt][3]);
        }
    }
}

// ---------------------------------------------------------------------------
// Fused small projections: b = h@W_b^T, a = h@W_a^T  (N=16 each).
// ---------------------------------------------------------------------------
__global__ __launch_bounds__(128) void small_proj_kernel(
    const float* __restrict__ hs,
    const float* __restrict__ W_b, const float* __restrict__ W_a)
{
    const int t = blockIdx.x;
    __shared__ float sh[HIDDEN];
    {
        const float4* hp = (const float4*)(hs + (size_t)t * HIDDEN);
        float4* sp = (float4*)sh;
        sp[threadIdx.x]       = hp[threadIdx.x];
        sp[threadIdx.x + 128] = hp[threadIdx.x + 128];
    }
    __syncthreads();

    const int out  = threadIdx.x >> 2;
    const int part = threadIdx.x & 3;
    const float* W = (out < 16) ? (W_b + (size_t)out * HIDDEN)
                                : (W_a + (size_t)(out - 16) * HIDDEN);
    const float4* W4 = (const float4*)(W + part * 256);
    const float4* S4 = (const float4*)(sh + part * 256);

    float a0 = 0.f, a1 = 0.f;
#pragma unroll 8
    for (int i = 0; i < 64; i += 2) {
        float4 w = W4[i],      s = S4[i];
        float4 w2 = W4[i + 1], s2 = S4[i + 1];
        a0 = fmaf(w.x, s.x, a0);   a0 = fmaf(w.y, s.y, a0);
        a0 = fmaf(w.z, s.z, a0);   a0 = fmaf(w.w, s.w, a0);
        a1 = fmaf(w2.x, s2.x, a1); a1 = fmaf(w2.y, s2.y, a1);
        a1 = fmaf(w2.z, s2.z, a1); a1 = fmaf(w2.w, s2.w, a1);
    }
    float acc = a0 + a1;
    acc += __shfl_xor_sync(0xffffffffu, acc, 1);
    acc += __shfl_xor_sync(0xffffffffu, acc, 2);
    if (part == 0) {
        if (out < 16) g_bbuf[t * HV + out] = acc;
        else          g_abuf[t * HV + (out - 16)] = acc;
    }
}

// ---------------------------------------------------------------------------
// Causal depthwise conv (KSZ=4) + silu + per-head L2 norm + gates.
// ---------------------------------------------------------------------------
__global__ __launch_bounds__(512) void conv_gate_kernel(
    const float* __restrict__ conv_w,
    const float* __restrict__ dt_bias, const float* __restrict__ A_log,
    const int* __restrict__ cu, int nseq)
{
    const int t = blockIdx.x;
    __shared__ float ybuf[CONV_DIM];
    __shared__ float ssq[16];

    int start = 0;
    for (int b = 0; b < nseq; b++) {
        int s = cu[b];
        if (t >= s) start = s;
    }

#pragma unroll
    for (int r = 0; r < 4; r++) {
        int c = threadIdx.x + 512 * r;
        float acc = 0.f;
#pragma unroll
        for (int j = 0; j < 4; j++) {
            int tt = t - 3 + j;
            if (tt >= start)
                acc = fmaf(conv_w[c * 4 + j], g_mixed[(size_t)tt * CONV_DIM + c], acc);
        }
        ybuf[c] = acc / (1.f + expf(-acc));
    }
    __syncthreads();

    {
        int w = threadIdx.x >> 5, lane = threadIdx.x & 31;
        float x0 = ybuf[w * 64 + lane];
        float x1 = ybuf[w * 64 + 32 + lane];
        float s2 = x0 * x0 + x1 * x1;
#pragma unroll
        for (int off = 16; off > 0; off >>= 1)
            s2 += __shfl_xor_sync(0xffffffffu, s2, off);
        if (lane == 0) ssq[w] = s2;
    }
    __syncthreads();

#pragma unroll
    for (int r = 0; r < 4; r++) {
        int c = threadIdx.x + 512 * r;
        float yv = ybuf[c];
        if (c < KEY_DIM) {
            int h = c >> 6;
            g_qn[(size_t)t * KEY_DIM + c] = yv * rsqrtf(ssq[h] + 1e-6f) * 0.125f;
        } else if (c < 2 * KEY_DIM) {
            int cc = c - KEY_DIM;
            int h = cc >> 6;
            g_kn[(size_t)t * KEY_DIM + cc] = yv * rsqrtf(ssq[8 + h] + 1e-6f);
        } else {
            g_vv[(size_t)t * VAL_DIM + (c - 2 * KEY_DIM)] = yv;
        }
    }

    if (threadIdx.x < HV) {
        int h = threadIdx.x;
        float bb = g_bbuf[t * HV + h];
        g_beta[t * HV + h] = 1.f / (1.f + expf(-bb));
        float aa = g_abuf[t * HV + h] + dt_bias[h];
        float sp = (aa > 20.f) ? aa : log1pf(expf(aa));
        g_gate[t * HV + h] = -expf(A_log[h]) * sp;
    }
}

// ---------------------------------------------------------------------------
// Gated delta rule recurrence — single pipelined shfl pass per step.
// o_t = dec*(q.S_old) + (q.k)*delta ; delta = b*(v - dec*(k.S_old)) ;
// S_new = dec*S_old + delta*k.
// grid (HV, nseq, 2); 128 threads: column c = tid>>2, row-group r = tid&3.
// ---------------------------------------------------------------------------
__global__ __launch_bounds__(128) void delta_kernel(const int* __restrict__ cu)
{
    const int h  = blockIdx.x;
    const int b  = blockIdx.y;
    const int j  = blockIdx.z * 32 + (threadIdx.x >> 2);
    const int r  = threadIdx.x & 3;
    const int i0 = r * 16;
    const int kh = h >> 1;
    const int start = cu[b], end = cu[b + 1];

    unsigned long long S2[8];
#pragma unroll
    for (int i = 0; i < 8; i++) S2[i] = 0ULL;

    unsigned long long K2[8], Q2[8], Kn[8], Qn[8];
    float vc, gc, bc, vn, gn, bn;

    auto loadT = [&](int t, unsigned long long* kk, unsigned long long* qq,
                     float& v_, float& g_, float& b_) {
        const ulonglong2* kp = (const ulonglong2*)(g_kn + (size_t)t * KEY_DIM + kh * DK + i0);
        const ulonglong2* qp = (const ulonglong2*)(g_qn + (size_t)t * KEY_DIM + kh * DK + i0);
#pragma unroll
        for (int m = 0; m < 4; m++) {
            ulonglong2 ku = kp[m], qu = qp[m];
            kk[2 * m] = ku.x; kk[2 * m + 1] = ku.y;
            qq[2 * m] = qu.x; qq[2 * m + 1] = qu.y;
        }
        v_ = g_vv[(size_t)t * VAL_DIM + h * DV + j];
        g_ = g_gate[t * HV + h];
        b_ = g_beta[t * HV + h];
    };

    if (start < end) loadT(start, K2, Q2, vc, gc, bc);

    for (int t = start; t < end; t++) {
        int tn = (t + 1 < end) ? (t + 1) : t;
        loadT(tn, Kn, Qn, vn, gn, bn);

        const float dec = expf(gc);

        unsigned long long pk0 = 0ULL, pk1 = 0ULL;
        unsigned long long pq0 = 0ULL, pq1 = 0ULL;
        unsigned long long pz0 = 0ULL, pz1 = 0ULL;
#pragma unroll
        for (int m = 0; m < 8; m += 2) {
            pk0 = fma2(K2[m],     S2[m],     pk0);
            pk1 = fma2(K2[m + 1], S2[m + 1], pk1);
            pq0 = fma2(Q2[m],     S2[m],     pq0);
            pq1 = fma2(Q2[m + 1], S2[m + 1], pq1);
            pz0 = fma2(Q2[m],     K2[m],     pz0);
            pz1 = fma2(Q2[m + 1], K2[m + 1], pz1);
        }
        float a0, a1, b0, b1;
        upk2(pk0, a0, a1); upk2(pk1, b0, b1);
        float pk = (a0 + a1) + (b0 + b1);
        upk2(pq0, a0, a1); upk2(pq1, b0, b1);
        float pq = (a0 + a1) + (b0 + b1);
        upk2(pz0, a0, a1); upk2(pz1, b0, b1);
        float pz = (a0 + a1) + (b0 + b1);

        pk += __shfl_xor_sync(0xffffffffu, pk, 1);
        pq += __shfl_xor_sync(0xffffffffu, pq, 1);
        pz += __shfl_xor_sync(0xffffffffu, pz, 1);
        pk += __shfl_xor_sync(0xffffffffu, pk, 2);
        pq += __shfl_xor_sync(0xffffffffu, pq, 2);
        pz += __shfl_xor_sync(0xffffffffu, pz, 2);

        const float delta = bc * (vc - dec * pk);
        if (r == 0)
            g_obuf[(size_t)t * VAL_DIM + h * DV + j] = dec * pq + delta * pz;

        const unsigned long long d2  = pk2(delta, delta);
        const unsigned long long dc2 = pk2(dec, dec);
#pragma unroll
        for (int m = 0; m < 8; m += 2) {
            S2[m]     = fma2(dc2, S2[m],     mul2(K2[m],     d2));
            S2[m + 1] = fma2(dc2, S2[m + 1], mul2(K2[m + 1], d2));
        }

#pragma unroll
        for (int m = 0; m < 8; m++) { K2[m] = Kn[m]; Q2[m] = Qn[m]; }
        vc = vn; gc = gn; bc = bn;
    }
}

// ---------------------------------------------------------------------------
// Gated RMSNorm; output stored as fp16 (feeds out-projection GEMM).
// ---------------------------------------------------------------------------
__global__ __launch_bounds__(256) void gated_norm_kernel(const float* __restrict__ nw)
{
    const int t = blockIdx.x;
    const int tid = threadIdx.x;
    const int h = tid >> 4;
    const int s = tid & 15;

    const size_t base = ((size_t)t * HV + h) * DV + s * 4;
    float4 o4 = *(const float4*)(g_obuf + base);
    float ss = o4.x * o4.x + o4.y * o4.y + o4.z * o4.z + o4.w * o4.w;
    ss += __shfl_xor_sync(0xffffffffu, ss, 8);
    ss += __shfl_xor_sync(0xffffffffu, ss, 4);
    ss += __shfl_xor_sync(0xffffffffu, ss, 2);
    ss += __shfl_xor_sync(0xffffffffu, ss, 1);
    const float rr = rsqrtf(ss * (1.f / 64.f) + 1e-6f);

    float4 z4 = *(const float4*)(g_zbuf + (size_t)t * VAL_DIM + h * DV + s * 4);
    float4 w4 = *(const float4*)(nw + s * 4);
    float ox = o4.x * rr * w4.x * (z4.x / (1.f + expf(-z4.x)));
    float oy = o4.y * rr * w4.y * (z4.y / (1.f + expf(-z4.y)));
    float oz = o4.z * rr * w4.z * (z4.z / (1.f + expf(-z4.z)));
    float ow = o4.w * rr * w4.w * (z4.w / (1.f + expf(-z4.w)));

    *(__half2*)(g_onh + base)     = __half2(__float2half_rn(ox), __float2half_rn(oy));
    *(__half2*)(g_onh + base + 2) = __half2(__float2half_rn(oz), __float2half_rn(ow));
}

// ---------------------------------------------------------------------------
extern "C" void kernel_launch(void* const* d_in, const int* in_sizes, int n_in,
                              void* d_out, int out_size)
{
    const float* hidden  = (const float*)d_in[0];
    const float* W_qkv   = (const float*)d_in[1];
    const float* W_z     = (const float*)d_in[2];
    const float* W_b     = (const float*)d_in[3];
    const float* W_a     = (const float*)d_in[4];
    const float* conv_w  = (const float*)d_in[5];
    const float* dt_bias = (const float*)d_in[6];
    const float* A_log   = (const float*)d_in[7];
    const float* nw      = (const float*)d_in[8];
    const float* W_out   = (const float*)d_in[9];
    const int*   cu      = (const int*)d_in[10];

    const int total = in_sizes[0] / HIDDEN;
    const int nseq  = in_sizes[10] - 1;

    float *mixed, *zb;
    __half *hh, *wqkvh, *wzh, *woh, *onh;
    cudaGetSymbolAddress((void**)&mixed, g_mixed);
    cudaGetSymbolAddress((void**)&zb,    g_zbuf);
    cudaGetSymbolAddress((void**)&hh,    g_hh);
    cudaGetSymbolAddress((void**)&wqkvh, g_wqkvh);
    cudaGetSymbolAddress((void**)&wzh,   g_wzh);
    cudaGetSymbolAddress((void**)&woh,   g_woh);
    cudaGetSymbolAddress((void**)&onh,   g_onh);

    const int smem_bytes = SMEM_W * 4;
    cudaFuncSetAttribute(gemm_fp16, cudaFuncAttributeMaxDynamicSharedMemorySize, smem_bytes);

    // 0. fp16 conversion pre-pass
    {
        int n4;
        n4 = total * HIDDEN / 4;
        cvt_h_kernel<<<(n4 + 255) / 256, 256>>>((const float4*)hidden, (__half2*)hh, n4);
        n4 = CONV_DIM * HIDDEN / 4;
        cvt_h_kernel<<<(n4 + 255) / 256, 256>>>((const float4*)W_qkv, (__half2*)wqkvh, n4);
        n4 = VAL_DIM * HIDDEN / 4;
        cvt_h_kernel<<<(n4 + 255) / 256, 256>>>((const float4*)W_z, (__half2*)wzh, n4);
        n4 = HIDDEN * VAL_DIM / 4;
        cvt_h_kernel<<<(n4 + 255) / 256, 256>>>((const float4*)W_out, (__half2*)woh, n4);
    }

    const int mB = (total + 127) / 128;

    // 1. big projections (single-term fp16 mma)
    gemm_fp16<<<dim3(CONV_DIM / 64, mB), 256, smem_bytes>>>(
        hh, wqkvh, mixed, total, CONV_DIM, HIDDEN);
    gemm_fp16<<<dim3(VAL_DIM / 64, mB), 256, smem_bytes>>>(
        hh, wzh, zb, total, VAL_DIM, HIDDEN);

    // 2. small projections (b, a fused)
    small_proj_kernel<<<total, 128>>>(hidden, W_b, W_a);

    // 3. conv + silu + norms + gates
    conv_gate_kernel<<<total, 512>>>(conv_w, dt_bias, A_log, cu, nseq);

    // 4. recurrence
    delta_kernel<<<dim3(HV, nseq, 2), 128>>>(cu);

    // 5. gated RMSNorm (fp16 output)
    gated_norm_kernel<<<total, 256>>>(nw);

    // 6. output projection
    gemm_fp16<<<dim3(VAL_DIM / 64, mB), 256, smem_bytes>>>(
        onh, woh, (float*)d_out, total, HIDDEN, HIDDEN);
}

// round 17
// speedup vs baseline: 1.3634x; 1.0678x over previous
#include <cuda_runtime.h>
#include <cuda_fp16.h>
#include <cuda_bf16.h>
#include <math.h>
#include <stdint.h>

// ---------------------------------------------------------------------------
// GatedDeltaNetVarlen  (total=1536, HIDDEN=1024, HK=8, HV=16, DK=DV=64, KSZ=4)
// R16: fp16 mma GEMM with ldmatrix fragment loads (4x fewer LDS instrs) +
// fused QKV+z projection (one N=3072 GEMM). Gates stay fp32.
// ---------------------------------------------------------------------------

#define TOTAL_MAX 1536
#define HIDDEN 1024
#define HK 8
#define HV 16
#define DK 64
#define DV 64
#define KEY_DIM 512
#define VAL_DIM 1024
#define CONV_DIM 2048
#define BIGN 3072            // CONV_DIM + VAL_DIM fused projection width

__device__ __align__(16) float g_big  [TOTAL_MAX * BIGN];   // mixed | z
__device__ __align__(16) float g_bbuf [TOTAL_MAX * HV];
__device__ __align__(16) float g_abuf [TOTAL_MAX * HV];
__device__ __align__(16) float g_qn   [TOTAL_MAX * KEY_DIM];
__device__ __align__(16) float g_kn   [TOTAL_MAX * KEY_DIM];
__device__ __align__(16) float g_vv   [TOTAL_MAX * VAL_DIM];
__device__ __align__(16) float g_beta [TOTAL_MAX * HV];
__device__ __align__(16) float g_gate [TOTAL_MAX * HV];
__device__ __align__(16) float g_obuf [TOTAL_MAX * VAL_DIM];
// fp16 copies
__device__ __align__(16) __half g_hh   [TOTAL_MAX * HIDDEN];
__device__ __align__(16) __half g_wbig [BIGN * HIDDEN];      // W_qkv ; W_z
__device__ __align__(16) __half g_woh  [HIDDEN * VAL_DIM];
__device__ __align__(16) __half g_onh  [TOTAL_MAX * VAL_DIM];

// ------------------------------ helpers ------------------------------------
__device__ __forceinline__ unsigned long long pk2(float a, float b) {
    unsigned long long r;
    asm("mov.b64 %0, {%1,%2};" : "=l"(r) : "f"(a), "f"(b));
    return r;
}
__device__ __forceinline__ void upk2(unsigned long long v, float& a, float& b) {
    asm("mov.b64 {%0,%1}, %2;" : "=f"(a), "=f"(b) : "l"(v));
}
__device__ __forceinline__ unsigned long long fma2(
    unsigned long long a, unsigned long long b, unsigned long long c) {
    unsigned long long d;
    asm("fma.rn.f32x2 %0, %1, %2, %3;" : "=l"(d) : "l"(a), "l"(b), "l"(c));
    return d;
}
__device__ __forceinline__ unsigned long long mul2(
    unsigned long long a, unsigned long long b) {
    unsigned long long d;
    asm("mul.rn.f32x2 %0, %1, %2;" : "=l"(d) : "l"(a), "l"(b));
    return d;
}
__device__ __forceinline__ void cpa16(uint32_t dst, const void* src, bool ok) {
    int sz = ok ? 16 : 0;
    asm volatile("cp.async.cg.shared.global [%0], [%1], 16, %2;"
                 :: "r"(dst), "l"(src), "r"(sz) : "memory");
}

// ---------------------------------------------------------------------------
// pre-pass: convert f32 -> fp16
// ---------------------------------------------------------------------------
__global__ __launch_bounds__(256) void cvt_h_kernel(
    const float4* __restrict__ s, __half2* __restrict__ d, int n4)
{
    int i = blockIdx.x * blockDim.x + threadIdx.x;
    if (i < n4) {
        float4 v = s[i];
        d[2 * i]     = __half2(__float2half_rn(v.x), __float2half_rn(v.y));
        d[2 * i + 1] = __half2(__float2half_rn(v.z), __float2half_rn(v.w));
    }
}

// ---------------------------------------------------------------------------
// fp16 GEMM with ldmatrix:  C[M,N] = A[M,K] * B[N,K]^T  (f32 accum)
// 256 threads (8 warps 4m x 2n), BM=128, BN=64, BK=32, warp tile 32x32.
// cp.async 3-stage pipeline; fragments via ldmatrix.m8n8.x4.
// Smem word = half2 kpair, row pitch 20 words (conflict-free phases).
// ---------------------------------------------------------------------------
#define PAD_W 20
#define AH_W (128 * PAD_W)
#define BH_W (64 * PAD_W)
#define STAGE_W (AH_W + BH_W)
#define STG 3
#define SMEM_W (STG * STAGE_W)

__global__ __launch_bounds__(256) void gemm_fp16(
    const __half* __restrict__ A, const __half* __restrict__ B,
    float* __restrict__ C, int M, int N, int K)
{
    extern __shared__ unsigned shm[];
    const uint32_t sbase = (uint32_t)__cvta_generic_to_shared(shm);

    const int tid  = threadIdx.x;
    const int lane = tid & 31;
    const int wid  = tid >> 5;
    const int wm   = wid >> 1;        // 0..3
    const int wn   = wid & 1;         // 0..1
    const int gid  = lane >> 2;       // 0..7
    const int tig  = lane & 3;        // 0..3

    // ldmatrix lane->address components
    const int la = lane & 15;               // A: row offset
    const int ka = (lane >> 4) << 2;        // A: k word offset (0 or 4)
    const int quad = lane >> 3;
    const int lb = ((quad >> 1) << 3) + (lane & 7);  // B: row offset
    const int kbB = (quad & 1) << 2;                 // B: k word offset

    const int m0 = blockIdx.y * 128;
    const int n0 = blockIdx.x * 64;

    const int arow = tid >> 1;        // 0..127
    const int ahalf = tid & 1;        // 0,1
    const int brow = tid >> 2;        // 0..63
    const int bchk = tid & 3;         // 0..3
    const int iters = K / 32;

    auto stage_in = [&](int it) {
        if (it < iters) {
            const int s  = it % STG;
            const int k0 = it * 32;
            const uint32_t sA = sbase + (s * STAGE_W) * 4;
            const uint32_t sB = sA + AH_W * 4;
            {
                bool ok = (m0 + arow) < M;
                const size_t go = (size_t)(m0 + arow) * K + k0 + ahalf * 16;
                const uint32_t wo = (arow * PAD_W + ahalf * 8) << 2;
                cpa16(sA + wo,      A + go,     ok);
                cpa16(sA + wo + 16, A + go + 8, ok);
            }
            {
                bool ok = (n0 + brow) < N;
                const size_t go = (size_t)(n0 + brow) * K + k0 + bchk * 8;
                cpa16(sB + ((brow * PAD_W + bchk * 4) << 2), B + go, ok);
            }
        }
        asm volatile("cp.async.commit_group;" ::: "memory");
    };

    float acc[2][4][4];
#pragma unroll
    for (int i = 0; i < 2; i++)
#pragma unroll
        for (int j = 0; j < 4; j++)
#pragma unroll
            for (int v = 0; v < 4; v++) acc[i][j][v] = 0.f;

    stage_in(0);
    stage_in(1);

#define MMA_F16(ai, bi) \
    asm volatile( \
        "mma.sync.aligned.m16n8k16.row.col.f32.f16.f16.f32 " \
        "{%0,%1,%2,%3}, {%4,%5,%6,%7}, {%8,%9}, {%0,%1,%2,%3};" \
        : "+f"(acc[mt][nt][0]), "+f"(acc[mt][nt][1]), \
          "+f"(acc[mt][nt][2]), "+f"(acc[mt][nt][3]) \
        : "r"(ai[mt][0]), "r"(ai[mt][1]), "r"(ai[mt][2]), "r"(ai[mt][3]), \
          "r"(bi[nt][0]), "r"(bi[nt][1]))

    for (int it = 0; it < iters; it++) {
        asm volatile("cp.async.wait_group 1;" ::: "memory");
        __syncthreads();
        stage_in(it + 2);

        const int s = it % STG;
        const uint32_t sAw = sbase + (s * STAGE_W) * 4;
        const uint32_t sBw = sAw + AH_W * 4;

#pragma unroll
        for (int ks = 0; ks < 2; ks++) {
            const int kb = ks * 8;
            unsigned af[2][4], bf[4][2];
            // A fragments: one ldmatrix.x4 per 16-row tile
#pragma unroll
            for (int mt = 0; mt < 2; mt++) {
                uint32_t addr = sAw +
                    (((wm * 32 + mt * 16 + la) * PAD_W + kb + ka) << 2);
                asm volatile(
                    "ldmatrix.sync.aligned.m8n8.x4.shared.b16 {%0,%1,%2,%3}, [%4];"
                    : "=r"(af[mt][0]), "=r"(af[mt][1]),
                      "=r"(af[mt][2]), "=r"(af[mt][3])
                    : "r"(addr));
            }
            // B fragments: one ldmatrix.x4 per pair of 8-row tiles
#pragma unroll
            for (int np = 0; np < 2; np++) {
                uint32_t addr = sBw +
                    (((wn * 32 + np * 16 + lb) * PAD_W + kb + kbB) << 2);
                unsigned r0, r1, r2, r3;
                asm volatile(
                    "ldmatrix.sync.aligned.m8n8.x4.shared.b16 {%0,%1,%2,%3}, [%4];"
                    : "=r"(r0), "=r"(r1), "=r"(r2), "=r"(r3)
                    : "r"(addr));
                bf[np * 2][0]     = r0;  // n-tile np*2,   k-lo
                bf[np * 2][1]     = r1;  // n-tile np*2,   k-hi
                bf[np * 2 + 1][0] = r2;  // n-tile np*2+1, k-lo
                bf[np * 2 + 1][1] = r3;  // n-tile np*2+1, k-hi
            }
#pragma unroll
            for (int mt = 0; mt < 2; mt++)
#pragma unroll
                for (int nt = 0; nt < 4; nt++) {
                    MMA_F16(af, bf);
                }
        }
    }

    // epilogue
#pragma unroll
    for (int mt = 0; mt < 2; mt++) {
        int row = m0 + wm * 32 + mt * 16 + gid;
#pragma unroll
        for (int nt = 0; nt < 4; nt++) {
            int col = n0 + wn * 32 + nt * 8 + tig * 2;
            if (row < M)
                *(float2*)(C + (size_t)row * N + col) =
                    make_float2(acc[mt][nt][0], acc[mt][nt][1]);
            if (row + 8 < M)
                *(float2*)(C + (size_t)(row + 8) * N + col) =
                    make_float2(acc[mt][nt][2], acc[mt][nt][3]);
        }
    }
}

// ---------------------------------------------------------------------------
// Fused small projections: b = h@W_b^T, a = h@W_a^T  (N=16 each, fp32).
// ---------------------------------------------------------------------------
__global__ __launch_bounds__(128) void small_proj_kernel(
    const float* __restrict__ hs,
    const float* __restrict__ W_b, const float* __restrict__ W_a)
{
    const int t = blockIdx.x;
    __shared__ float sh[HIDDEN];
    {
        const float4* hp = (const float4*)(hs + (size_t)t * HIDDEN);
        float4* sp = (float4*)sh;
        sp[threadIdx.x]       = hp[threadIdx.x];
        sp[threadIdx.x + 128] = hp[threadIdx.x + 128];
    }
    __syncthreads();

    const int out  = threadIdx.x >> 2;
    const int part = threadIdx.x & 3;
    const float* W = (out < 16) ? (W_b + (size_t)out * HIDDEN)
                                : (W_a + (size_t)(out - 16) * HIDDEN);
    const float4* W4 = (const float4*)(W + part * 256);
    const float4* S4 = (const float4*)(sh + part * 256);

    float a0 = 0.f, a1 = 0.f;
#pragma unroll 8
    for (int i = 0; i < 64; i += 2) {
        float4 w = W4[i],      s = S4[i];
        float4 w2 = W4[i + 1], s2 = S4[i + 1];
        a0 = fmaf(w.x, s.x, a0);   a0 = fmaf(w.y, s.y, a0);
        a0 = fmaf(w.z, s.z, a0);   a0 = fmaf(w.w, s.w, a0);
        a1 = fmaf(w2.x, s2.x, a1); a1 = fmaf(w2.y, s2.y, a1);
        a1 = fmaf(w2.z, s2.z, a1); a1 = fmaf(w2.w, s2.w, a1);
    }
    float acc = a0 + a1;
    acc += __shfl_xor_sync(0xffffffffu, acc, 1);
    acc += __shfl_xor_sync(0xffffffffu, acc, 2);
    if (part == 0) {
        if (out < 16) g_bbuf[t * HV + out] = acc;
        else          g_abuf[t * HV + (out - 16)] = acc;
    }
}

// ---------------------------------------------------------------------------
// Causal depthwise conv (KSZ=4) + silu + per-head L2 norm + gates.
// Reads mixed from g_big (row stride BIGN).
// ---------------------------------------------------------------------------
__global__ __launch_bounds__(512) void conv_gate_kernel(
    const float* __restrict__ conv_w,
    const float* __restrict__ dt_bias, const float* __restrict__ A_log,
    const int* __restrict__ cu, int nseq)
{
    const int t = blockIdx.x;
    __shared__ float ybuf[CONV_DIM];
    __shared__ float ssq[16];

    int start = 0;
    for (int b = 0; b < nseq; b++) {
        int s = cu[b];
        if (t >= s) start = s;
    }

#pragma unroll
    for (int r = 0; r < 4; r++) {
        int c = threadIdx.x + 512 * r;
        float acc = 0.f;
#pragma unroll
        for (int j = 0; j < 4; j++) {
            int tt = t - 3 + j;
            if (tt >= start)
                acc = fmaf(conv_w[c * 4 + j], g_big[(size_t)tt * BIGN + c], acc);
        }
        ybuf[c] = acc / (1.f + expf(-acc));
    }
    __syncthreads();

    {
        int w = threadIdx.x >> 5, lane = threadIdx.x & 31;
        float x0 = ybuf[w * 64 + lane];
        float x1 = ybuf[w * 64 + 32 + lane];
        float s2 = x0 * x0 + x1 * x1;
#pragma unroll
        for (int off = 16; off > 0; off >>= 1)
            s2 += __shfl_xor_sync(0xffffffffu, s2, off);
        if (lane == 0) ssq[w] = s2;
    }
    __syncthreads();

#pragma unroll
    for (int r = 0; r < 4; r++) {
        int c = threadIdx.x + 512 * r;
        float yv = ybuf[c];
        if (c < KEY_DIM) {
            int h = c >> 6;
            g_qn[(size_t)t * KEY_DIM + c] = yv * rsqrtf(ssq[h] + 1e-6f) * 0.125f;
        } else if (c < 2 * KEY_DIM) {
            int cc = c - KEY_DIM;
            int h = cc >> 6;
            g_kn[(size_t)t * KEY_DIM + cc] = yv * rsqrtf(ssq[8 + h] + 1e-6f);
        } else {
            g_vv[(size_t)t * VAL_DIM + (c - 2 * KEY_DIM)] = yv;
        }
    }

    if (threadIdx.x < HV) {
        int h = threadIdx.x;
        float bb = g_bbuf[t * HV + h];
        g_beta[t * HV + h] = 1.f / (1.f + expf(-bb));
        float aa = g_abuf[t * HV + h] + dt_bias[h];
        float sp = (aa > 20.f) ? aa : log1pf(expf(aa));
        g_gate[t * HV + h] = -expf(A_log[h]) * sp;
    }
}

// ---------------------------------------------------------------------------
// Gated delta rule recurrence — single pipelined shfl pass per step.
// ---------------------------------------------------------------------------
__global__ __launch_bounds__(128) void delta_kernel(const int* __restrict__ cu)
{
    const int h  = blockIdx.x;
    const int b  = blockIdx.y;
    const int j  = blockIdx.z * 32 + (threadIdx.x >> 2);
    const int r  = threadIdx.x & 3;
    const int i0 = r * 16;
    const int kh = h >> 1;
    const int start = cu[b], end = cu[b + 1];

    unsigned long long S2[8];
#pragma unroll
    for (int i = 0; i < 8; i++) S2[i] = 0ULL;

    unsigned long long K2[8], Q2[8], Kn[8], Qn[8];
    float vc, gc, bc, vn, gn, bn;

    auto loadT = [&](int t, unsigned long long* kk, unsigned long long* qq,
                     float& v_, float& g_, float& b_) {
        const ulonglong2* kp = (const ulonglong2*)(g_kn + (size_t)t * KEY_DIM + kh * DK + i0);
        const ulonglong2* qp = (const ulonglong2*)(g_qn + (size_t)t * KEY_DIM + kh * DK + i0);
#pragma unroll
        for (int m = 0; m < 4; m++) {
            ulonglong2 ku = kp[m], qu = qp[m];
            kk[2 * m] = ku.x; kk[2 * m + 1] = ku.y;
            qq[2 * m] = qu.x; qq[2 * m + 1] = qu.y;
        }
        v_ = g_vv[(size_t)t * VAL_DIM + h * DV + j];
        g_ = g_gate[t * HV + h];
        b_ = g_beta[t * HV + h];
    };

    if (start < end) loadT(start, K2, Q2, vc, gc, bc);

    for (int t = start; t < end; t++) {
        int tn = (t + 1 < end) ? (t + 1) : t;
        loadT(tn, Kn, Qn, vn, gn, bn);

        const float dec = expf(gc);

        unsigned long long pk0 = 0ULL, pk1 = 0ULL;
        unsigned long long pq0 = 0ULL, pq1 = 0ULL;
        unsigned long long pz0 = 0ULL, pz1 = 0ULL;
#pragma unroll
        for (int m = 0; m < 8; m += 2) {
            pk0 = fma2(K2[m],     S2[m],     pk0);
            pk1 = fma2(K2[m + 1], S2[m + 1], pk1);
            pq0 = fma2(Q2[m],     S2[m],     pq0);
            pq1 = fma2(Q2[m + 1], S2[m + 1], pq1);
            pz0 = fma2(Q2[m],     K2[m],     pz0);
            pz1 = fma2(Q2[m + 1], K2[m + 1], pz1);
        }
        float a0, a1, b0, b1;
        upk2(pk0, a0, a1); upk2(pk1, b0, b1);
        float pk = (a0 + a1) + (b0 + b1);
        upk2(pq0, a0, a1); upk2(pq1, b0, b1);
        float pq = (a0 + a1) + (b0 + b1);
        upk2(pz0, a0, a1); upk2(pz1, b0, b1);
        float pz = (a0 + a1) + (b0 + b1);

        pk += __shfl_xor_sync(0xffffffffu, pk, 1);
        pq += __shfl_xor_sync(0xffffffffu, pq, 1);
        pz += __shfl_xor_sync(0xffffffffu, pz, 1);
        pk += __shfl_xor_sync(0xffffffffu, pk, 2);
        pq += __shfl_xor_sync(0xffffffffu, pq, 2);
        pz += __shfl_xor_sync(0xffffffffu, pz, 2);

        const float delta = bc * (vc - dec * pk);
        if (r == 0)
            g_obuf[(size_t)t * VAL_DIM + h * DV + j] = dec * pq + delta * pz;

        const unsigned long long d2  = pk2(delta, delta);
        const unsigned long long dc2 = pk2(dec, dec);
#pragma unroll
        for (int m = 0; m < 8; m += 2) {
            S2[m]     = fma2(dc2, S2[m],     mul2(K2[m],     d2));
            S2[m + 1] = fma2(dc2, S2[m + 1], mul2(K2[m + 1], d2));
        }

#pragma unroll
        for (int m = 0; m < 8; m++) { K2[m] = Kn[m]; Q2[m] = Qn[m]; }
        vc = vn; gc = gn; bc = bn;
    }
}

// ---------------------------------------------------------------------------
// Gated RMSNorm; z read from g_big (+2048); output stored as fp16.
// ---------------------------------------------------------------------------
__global__ __launch_bounds__(256) void gated_norm_kernel(const float* __restrict__ nw)
{
    const int t = blockIdx.x;
    const int tid = threadIdx.x;
    const int h = tid >> 4;
    const int s = tid & 15;

    const size_t base = ((size_t)t * HV + h) * DV + s * 4;
    float4 o4 = *(const float4*)(g_obuf + base);
    float ss = o4.x * o4.x + o4.y * o4.y + o4.z * o4.z + o4.w * o4.w;
    ss += __shfl_xor_sync(0xffffffffu, ss, 8);
    ss += __shfl_xor_sync(0xffffffffu, ss, 4);
    ss += __shfl_xor_sync(0xffffffffu, ss, 2);
    ss += __shfl_xor_sync(0xffffffffu, ss, 1);
    const float rr = rsqrtf(ss * (1.f / 64.f) + 1e-6f);

    float4 z4 = *(const float4*)(g_big + (size_t)t * BIGN + CONV_DIM + h * DV + s * 4);
    float4 w4 = *(const float4*)(nw + s * 4);
    float ox = o4.x * rr * w4.x * (z4.x / (1.f + expf(-z4.x)));
    float oy = o4.y * rr * w4.y * (z4.y / (1.f + expf(-z4.y)));
    float oz = o4.z * rr * w4.z * (z4.z / (1.f + expf(-z4.z)));
    float ow = o4.w * rr * w4.w * (z4.w / (1.f + expf(-z4.w)));

    *(__half2*)(g_onh + base)     = __half2(__float2half_rn(ox), __float2half_rn(oy));
    *(__half2*)(g_onh + base + 2) = __half2(__float2half_rn(oz), __float2half_rn(ow));
}

// ---------------------------------------------------------------------------
extern "C" void kernel_launch(void* const* d_in, const int* in_sizes, int n_in,
                              void* d_out, int out_size)
{
    const float* hidden  = (const float*)d_in[0];
    const float* W_qkv   = (const float*)d_in[1];
    const float* W_z     = (const float*)d_in[2];
    const float* W_b     = (const float*)d_in[3];
    const float* W_a     = (const float*)d_in[4];
    const float* conv_w  = (const float*)d_in[5];
    const float* dt_bias = (const float*)d_in[6];
    const float* A_log   = (const float*)d_in[7];
    const float* nw      = (const float*)d_in[8];
    const float* W_out   = (const float*)d_in[9];
    const int*   cu      = (const int*)d_in[10];

    const int total = in_sizes[0] / HIDDEN;
    const int nseq  = in_sizes[10] - 1;

    float* big;
    __half *hh, *wbig, *woh, *onh;
    cudaGetSymbolAddress((void**)&big,  g_big);
    cudaGetSymbolAddress((void**)&hh,   g_hh);
    cudaGetSymbolAddress((void**)&wbig, g_wbig);
    cudaGetSymbolAddress((void**)&woh,  g_woh);
    cudaGetSymbolAddress((void**)&onh,  g_onh);

    const int smem_bytes = SMEM_W * 4;
    cudaFuncSetAttribute(gemm_fp16, cudaFuncAttributeMaxDynamicSharedMemorySize, smem_bytes);

    // 0. fp16 conversion pre-pass (W_qkv and W_z into one fused buffer)
    {
        int n4;
        n4 = total * HIDDEN / 4;
        cvt_h_kernel<<<(n4 + 255) / 256, 256>>>((const float4*)hidden, (__half2*)hh, n4);
        n4 = CONV_DIM * HIDDEN / 4;
        cvt_h_kernel<<<(n4 + 255) / 256, 256>>>((const float4*)W_qkv, (__half2*)wbig, n4);
        n4 = VAL_DIM * HIDDEN / 4;
        cvt_h_kernel<<<(n4 + 255) / 256, 256>>>(
            (const float4*)W_z, (__half2*)(wbig + (size_t)CONV_DIM * HIDDEN), n4);
        n4 = HIDDEN * VAL_DIM / 4;
        cvt_h_kernel<<<(n4 + 255) / 256, 256>>>((const float4*)W_out, (__half2*)woh, n4);
    }

    const int mB = (total + 127) / 128;

    // 1. fused QKV+z projection (N = 3072)
    gemm_fp16<<<dim3(BIGN / 64, mB), 256, smem_bytes>>>(
        hh, wbig, big, total, BIGN, HIDDEN);

    // 2. small projections (b, a; full fp32 — gates are error-sensitive)
    small_proj_kernel<<<total, 128>>>(hidden, W_b, W_a);

    // 3. conv + silu + norms + gates
    conv_gate_kernel<<<total, 512>>>(conv_w, dt_bias, A_log, cu, nseq);

    // 4. recurrence
    delta_kernel<<<dim3(HV, nseq, 2), 128>>>(cu);

    // 5. gated RMSNorm (fp16 output)
    gated_norm_kernel<<<total, 256>>>(nw);

    // 6. output projection
    gemm_fp16<<<dim3(VAL_DIM / 64, mB), 256, smem_bytes>>>(
        onh, woh, (float*)d_out, total, HIDDEN, HIDDEN);
}